// round 3
// baseline (speedup 1.0000x reference)
#include <cuda_runtime.h>
#include <math.h>

// Problem constants
#define BB 2
#define SSEQ 2048
#define DD 1024
#define HH 16
#define HD 64
#define FF 4096
#define NL 8
#define NT (BB*SSEQ)   // 4096 token rows

// ---------------- scratch (device globals: allocation-guard safe) ----------
__device__ float g_x  [NT*DD];          // residual stream (16 MB)
__device__ float g_h  [NT*DD];          // layernorm output (16 MB)
__device__ float g_q  [NT*DD];          // Q (16 MB)
__device__ float g_kv [NT*2*DD];        // K|V (32 MB)
__device__ float g_att[NT*DD];          // attention heads out (16 MB)
__device__ float g_f  [NT*FF];          // FFN hidden (64 MB)
__device__ float g_s  [134217728];      // scores B*H*S*S (512 MB)

// ---------------- helpers --------------------------------------------------
__device__ __forceinline__ float softplus_f(float x) {
    return fmaxf(x, 0.0f) + log1pf(expf(-fabsf(x)));
}

// ---------------- LayerNorm: one block per row (D=1024, 256 thr x float4) --
__global__ void ln_kernel(const float* __restrict__ in,
                          const float* __restrict__ gamma,
                          const float* __restrict__ beta,
                          float* __restrict__ out)
{
    int row = blockIdx.x;
    int tid = threadIdx.x;
    const float* p = in + (size_t)row * DD;
    float4 v = *(const float4*)(p + tid * 4);
    float s  = v.x + v.y + v.z + v.w;
    float sq = v.x*v.x + v.y*v.y + v.z*v.z + v.w*v.w;

    __shared__ float sm1[8], sm2[8];
    #pragma unroll
    for (int o = 16; o > 0; o >>= 1) {
        s  += __shfl_xor_sync(0xffffffffu, s,  o);
        sq += __shfl_xor_sync(0xffffffffu, sq, o);
    }
    if ((tid & 31) == 0) { sm1[tid >> 5] = s; sm2[tid >> 5] = sq; }
    __syncthreads();
    if (tid < 32) {
        s  = (tid < 8) ? sm1[tid] : 0.0f;
        sq = (tid < 8) ? sm2[tid] : 0.0f;
        #pragma unroll
        for (int o = 4; o > 0; o >>= 1) {
            s  += __shfl_xor_sync(0xffffffffu, s,  o);
            sq += __shfl_xor_sync(0xffffffffu, sq, o);
        }
        if (tid == 0) { sm1[0] = s; sm2[0] = sq; }
    }
    __syncthreads();
    float mean = sm1[0] * (1.0f / DD);
    float var  = sm2[0] * (1.0f / DD) - mean * mean;
    float rs   = rsqrtf(var + 1e-3f);

    float4 g  = *(const float4*)(gamma + tid * 4);
    float4 be = *(const float4*)(beta  + tid * 4);
    float4 o4;
    o4.x = (v.x - mean) * rs * g.x + be.x;
    o4.y = (v.y - mean) * rs * g.y + be.y;
    o4.z = (v.z - mean) * rs * g.z + be.z;
    o4.w = (v.w - mean) * rs * g.w + be.w;
    *(float4*)(out + (size_t)row * DD + tid * 4) = o4;
}

// ---------------- SGEMM 128x128x8, 256 thr, 8x8/thread ---------------------
// C[N,M] = A[N,K] @ B[K,M] + bias, epi: 0=bias, 1=bias+softplus, 2=bias+res
__global__ void __launch_bounds__(256) sgemm_kernel(
    const float* __restrict__ A, const float* __restrict__ B,
    const float* __restrict__ bias, const float* __restrict__ res,
    float* __restrict__ C, int N, int K, int M, int epi)
{
    __shared__ float As[8][128];   // As[k][m] (transposed)
    __shared__ float Bs[8][128];   // Bs[k][n]

    int tid = threadIdx.x;
    int bx = blockIdx.x, by = blockIdx.y;
    int a_row = tid >> 1;            // 0..127
    int a_col = (tid & 1) * 4;       // 0 or 4
    int b_row = tid >> 5;            // 0..7
    int b_col = (tid & 31) * 4;      // 0..124
    int tx = tid & 15, ty = tid >> 4;

    const float* Ap = A + (size_t)(by * 128 + a_row) * K + a_col;
    const float* Bp = B + (size_t)b_row * M + bx * 128 + b_col;

    float4 af = *(const float4*)Ap;
    float4 bf = *(const float4*)Bp;

    float acc[8][8];
    #pragma unroll
    for (int i = 0; i < 8; i++)
        #pragma unroll
        for (int j = 0; j < 8; j++) acc[i][j] = 0.0f;

    for (int k0 = 0; k0 < K; k0 += 8) {
        As[a_col + 0][a_row] = af.x;
        As[a_col + 1][a_row] = af.y;
        As[a_col + 2][a_row] = af.z;
        As[a_col + 3][a_row] = af.w;
        *(float4*)&Bs[b_row][b_col] = bf;
        __syncthreads();

        if (k0 + 8 < K) {
            af = *(const float4*)(Ap + k0 + 8);
            bf = *(const float4*)(Bp + (size_t)(k0 + 8) * M);
        }

        #pragma unroll
        for (int kk = 0; kk < 8; kk++) {
            float ar[8], br[8];
            ((float4*)ar)[0] = *(const float4*)&As[kk][ty * 4];
            ((float4*)ar)[1] = *(const float4*)&As[kk][64 + ty * 4];
            ((float4*)br)[0] = *(const float4*)&Bs[kk][tx * 4];
            ((float4*)br)[1] = *(const float4*)&Bs[kk][64 + tx * 4];
            #pragma unroll
            for (int i = 0; i < 8; i++)
                #pragma unroll
                for (int j = 0; j < 8; j++)
                    acc[i][j] += ar[i] * br[j];
        }
        __syncthreads();
    }

    // epilogue: rows map i<4 -> ty*4+i, i>=4 -> 64+ty*4+(i-4); cols similarly
    #pragma unroll
    for (int i = 0; i < 8; i++) {
        int r = by * 128 + ((i < 4) ? (ty * 4 + i) : (64 + ty * 4 + (i - 4)));
        #pragma unroll
        for (int jc = 0; jc < 2; jc++) {
            int c = bx * 128 + jc * 64 + tx * 4;
            float4 b4 = *(const float4*)(bias + c);
            float4 o;
            o.x = acc[i][jc * 4 + 0] + b4.x;
            o.y = acc[i][jc * 4 + 1] + b4.y;
            o.z = acc[i][jc * 4 + 2] + b4.z;
            o.w = acc[i][jc * 4 + 3] + b4.w;
            if (epi == 1) {
                o.x = softplus_f(o.x); o.y = softplus_f(o.y);
                o.z = softplus_f(o.z); o.w = softplus_f(o.w);
            } else if (epi == 2) {
                float4 r4 = *(const float4*)(res + (size_t)r * M + c);
                o.x += r4.x; o.y += r4.y; o.z += r4.z; o.w += r4.w;
            }
            *(float4*)(C + (size_t)r * M + c) = o;
        }
    }
}

// ---------------- attention scores: 64x64 tile, K=64, causal skip ----------
// scores[bh,q,k] = (Q.K)/8 + slope*(k-q)  (only tiles kt<=qt are written)
__global__ void __launch_bounds__(256) score_kernel(
    const float* __restrict__ q, const float* __restrict__ kv,
    float* __restrict__ sc)
{
    int kt = blockIdx.x, qt = blockIdx.y, bh = blockIdx.z;
    if (kt > qt) return;
    int b = bh >> 4, h = bh & 15;

    __shared__ float Qs[64][68];   // [d][qrow]
    __shared__ float Ks[64][68];   // [d][kcol]
    int tid = threadIdx.x;
    int r0 = tid >> 4;             // 0..15
    int d0 = (tid & 15) * 4;
    int tx = tid & 15, ty = tid >> 4;

    const float* qbase = q  + (size_t)b * SSEQ * DD       + h * HD;
    const float* kbase = kv + (size_t)b * SSEQ * (2 * DD) + h * HD;

    #pragma unroll
    for (int i = 0; i < 4; i++) {
        int row = r0 + i * 16;
        float4 qa = *(const float4*)(qbase + (size_t)(qt * 64 + row) * DD + d0);
        Qs[d0 + 0][row] = qa.x; Qs[d0 + 1][row] = qa.y;
        Qs[d0 + 2][row] = qa.z; Qs[d0 + 3][row] = qa.w;
        float4 ka = *(const float4*)(kbase + (size_t)(kt * 64 + row) * (2 * DD) + d0);
        Ks[d0 + 0][row] = ka.x; Ks[d0 + 1][row] = ka.y;
        Ks[d0 + 2][row] = ka.z; Ks[d0 + 3][row] = ka.w;
    }
    __syncthreads();

    float acc[4][4];
    #pragma unroll
    for (int i = 0; i < 4; i++)
        #pragma unroll
        for (int j = 0; j < 4; j++) acc[i][j] = 0.0f;

    #pragma unroll 16
    for (int kk = 0; kk < 64; kk++) {
        float4 a = *(const float4*)&Qs[kk][ty * 4];
        float4 c = *(const float4*)&Ks[kk][tx * 4];
        float ar[4] = {a.x, a.y, a.z, a.w};
        float cr[4] = {c.x, c.y, c.z, c.w};
        #pragma unroll
        for (int i = 0; i < 4; i++)
            #pragma unroll
            for (int j = 0; j < 4; j++)
                acc[i][j] += ar[i] * cr[j];
    }

    float slope = exp2f(-0.5f * (float)(h + 1));
    #pragma unroll
    for (int i = 0; i < 4; i++) {
        int qrow = qt * 64 + ty * 4 + i;
        float* out = sc + ((size_t)bh * SSEQ + qrow) * SSEQ + kt * 64 + tx * 4;
        float4 o;
        int k0 = kt * 64 + tx * 4;
        o.x = acc[i][0] * 0.125f + slope * (float)(k0 + 0 - qrow);
        o.y = acc[i][1] * 0.125f + slope * (float)(k0 + 1 - qrow);
        o.z = acc[i][2] * 0.125f + slope * (float)(k0 + 2 - qrow);
        o.w = acc[i][3] * 0.125f + slope * (float)(k0 + 3 - qrow);
        *(float4*)out = o;
    }
}

// ---------------- causal softmax, register-resident row --------------------
__global__ void __launch_bounds__(256) softmax_kernel(float* __restrict__ sc)
{
    int qrow = blockIdx.x;
    int bh   = blockIdx.y;
    float* row = sc + ((size_t)bh * SSEQ + qrow) * SSEQ;
    int tid  = threadIdx.x;
    int Lpad = ((qrow >> 6) + 1) << 6;     // round_up(qrow+1, 64)

    float4 v[2];
    int k0s[2];
    float mx = -1e30f;
    #pragma unroll
    for (int c = 0; c < 2; c++) {
        int k0 = (tid + c * 256) * 4;
        k0s[c] = k0;
        if (k0 < Lpad) {
            float4 t = *(float4*)(row + k0);
            t.x = (k0 + 0 <= qrow) ? t.x : -1e30f;
            t.y = (k0 + 1 <= qrow) ? t.y : -1e30f;
            t.z = (k0 + 2 <= qrow) ? t.z : -1e30f;
            t.w = (k0 + 3 <= qrow) ? t.w : -1e30f;
            v[c] = t;
            mx = fmaxf(mx, fmaxf(fmaxf(t.x, t.y), fmaxf(t.z, t.w)));
        }
    }

    __shared__ float sm[8];
    #pragma unroll
    for (int o = 16; o > 0; o >>= 1) mx = fmaxf(mx, __shfl_xor_sync(0xffffffffu, mx, o));
    if ((tid & 31) == 0) sm[tid >> 5] = mx;
    __syncthreads();
    if (tid < 32) {
        mx = (tid < 8) ? sm[tid] : -1e30f;
        #pragma unroll
        for (int o = 4; o > 0; o >>= 1) mx = fmaxf(mx, __shfl_xor_sync(0xffffffffu, mx, o));
        if (tid == 0) sm[0] = mx;
    }
    __syncthreads();
    mx = sm[0];
    __syncthreads();   // protect sm before reuse

    float s = 0.0f;
    #pragma unroll
    for (int c = 0; c < 2; c++) {
        if (k0s[c] < Lpad) {
            v[c].x = expf(v[c].x - mx);
            v[c].y = expf(v[c].y - mx);
            v[c].z = expf(v[c].z - mx);
            v[c].w = expf(v[c].w - mx);
            s += v[c].x + v[c].y + v[c].z + v[c].w;
        }
    }
    #pragma unroll
    for (int o = 16; o > 0; o >>= 1) s += __shfl_xor_sync(0xffffffffu, s, o);
    if ((tid & 31) == 0) sm[tid >> 5] = s;
    __syncthreads();
    if (tid < 32) {
        s = (tid < 8) ? sm[tid] : 0.0f;
        #pragma unroll
        for (int o = 4; o > 0; o >>= 1) s += __shfl_xor_sync(0xffffffffu, s, o);
        if (tid == 0) sm[0] = s;
    }
    __syncthreads();
    float inv = 1.0f / sm[0];

    #pragma unroll
    for (int c = 0; c < 2; c++) {
        if (k0s[c] < Lpad) {
            float4 t = v[c];
            t.x *= inv; t.y *= inv; t.z *= inv; t.w *= inv;
            *(float4*)(row + k0s[c]) = t;
        }
    }
}

// ---------------- A.V: 64 q-rows x 64 head-dims, causal k-loop -------------
__global__ void __launch_bounds__(256) av_kernel(
    const float* __restrict__ sc, const float* __restrict__ kv,
    float* __restrict__ o)
{
    int qt = blockIdx.x;
    int bh = blockIdx.y;
    int b = bh >> 4, h = bh & 15;

    __shared__ float As[64][68];   // [k][qrow]
    __shared__ float Vs[64][68];   // [k][d]
    int tid = threadIdx.x;
    int r0 = tid >> 4;
    int d0 = (tid & 15) * 4;
    int tx = tid & 15, ty = tid >> 4;

    const float* abase = sc + ((size_t)bh * SSEQ + qt * 64) * SSEQ;
    const float* vbase = kv + (size_t)b * SSEQ * (2 * DD) + DD + h * HD;

    float acc[4][4];
    #pragma unroll
    for (int i = 0; i < 4; i++)
        #pragma unroll
        for (int j = 0; j < 4; j++) acc[i][j] = 0.0f;

    for (int kt = 0; kt <= qt; kt++) {
        #pragma unroll
        for (int i = 0; i < 4; i++) {
            int row = r0 + i * 16;
            float4 a = *(const float4*)(abase + (size_t)row * SSEQ + kt * 64 + d0);
            As[d0 + 0][row] = a.x; As[d0 + 1][row] = a.y;
            As[d0 + 2][row] = a.z; As[d0 + 3][row] = a.w;
            float4 vv = *(const float4*)(vbase + (size_t)(kt * 64 + row) * (2 * DD) + d0);
            *(float4*)&Vs[row][d0] = vv;
        }
        __syncthreads();
        #pragma unroll 16
        for (int kk = 0; kk < 64; kk++) {
            float4 a = *(const float4*)&As[kk][ty * 4];
            float4 vv = *(const float4*)&Vs[kk][tx * 4];
            float ar[4] = {a.x, a.y, a.z, a.w};
            float vr[4] = {vv.x, vv.y, vv.z, vv.w};
            #pragma unroll
            for (int i = 0; i < 4; i++)
                #pragma unroll
                for (int j = 0; j < 4; j++)
                    acc[i][j] += ar[i] * vr[j];
        }
        __syncthreads();
    }

    #pragma unroll
    for (int i = 0; i < 4; i++) {
        int qrow = qt * 64 + ty * 4 + i;
        float4 ov = {acc[i][0], acc[i][1], acc[i][2], acc[i][3]};
        *(float4*)(o + ((size_t)b * SSEQ + qrow) * DD + h * HD + tx * 4) = ov;
    }
}

// ---------------- host orchestration ---------------------------------------
extern "C" void kernel_launch(void* const* d_in, const int* in_sizes, int n_in,
                              void* d_out, int out_size)
{
    const float *ts, *fg, *fb, *wq, *bq, *wkv, *bkv, *wo, *bo,
                *w1, *b1, *w2, *b2, *ag, *ab, *ffg, *ffb;
    if (in_sizes[1] == 1024) {
        // setup_inputs dict order
        ts  = (const float*)d_in[0];
        fg  = (const float*)d_in[1];  fb  = (const float*)d_in[2];
        wq  = (const float*)d_in[3];  bq  = (const float*)d_in[4];
        wkv = (const float*)d_in[5];  bkv = (const float*)d_in[6];
        wo  = (const float*)d_in[7];  bo  = (const float*)d_in[8];
        w1  = (const float*)d_in[9];  b1  = (const float*)d_in[10];
        w2  = (const float*)d_in[11]; b2  = (const float*)d_in[12];
        ag  = (const float*)d_in[13]; ab  = (const float*)d_in[14];
        ffg = (const float*)d_in[15]; ffb = (const float*)d_in[16];
    } else {
        // reference() signature order
        ts  = (const float*)d_in[0];
        wq  = (const float*)d_in[1];  bq  = (const float*)d_in[2];
        wkv = (const float*)d_in[3];  bkv = (const float*)d_in[4];
        wo  = (const float*)d_in[5];  bo  = (const float*)d_in[6];
        w1  = (const float*)d_in[7];  b1  = (const float*)d_in[8];
        w2  = (const float*)d_in[9];  b2  = (const float*)d_in[10];
        ag  = (const float*)d_in[11]; ab  = (const float*)d_in[12];
        ffg = (const float*)d_in[13]; ffb = (const float*)d_in[14];
        fg  = (const float*)d_in[15]; fb  = (const float*)d_in[16];
    }

    float *x, *h, *q, *kv, *att, *f, *s;
    cudaGetSymbolAddress((void**)&x,   g_x);
    cudaGetSymbolAddress((void**)&h,   g_h);
    cudaGetSymbolAddress((void**)&q,   g_q);
    cudaGetSymbolAddress((void**)&kv,  g_kv);
    cudaGetSymbolAddress((void**)&att, g_att);
    cudaGetSymbolAddress((void**)&f,   g_f);
    cudaGetSymbolAddress((void**)&s,   g_s);

    cudaMemcpyAsync(x, ts, sizeof(float) * (size_t)NT * DD,
                    cudaMemcpyDeviceToDevice, 0);

    for (int l = 0; l < NL; l++) {
        // pre-attention LN
        ln_kernel<<<NT, 256>>>(x, ag + (size_t)l * DD, ab + (size_t)l * DD, h);
        // Q = h@wq + bq
        sgemm_kernel<<<dim3(DD / 128, NT / 128), 256>>>(
            h, wq + (size_t)l * DD * DD, bq + (size_t)l * DD, nullptr,
            q, NT, DD, DD, 0);
        // KV = h@wkv + bkv
        sgemm_kernel<<<dim3(2 * DD / 128, NT / 128), 256>>>(
            h, wkv + (size_t)l * DD * 2 * DD, bkv + (size_t)l * 2 * DD, nullptr,
            kv, NT, DD, 2 * DD, 0);
        // scores (causal tiles only) + ALiBi
        score_kernel<<<dim3(SSEQ / 64, SSEQ / 64, BB * HH), 256>>>(q, kv, s);
        // causal softmax
        softmax_kernel<<<dim3(SSEQ, BB * HH), 256>>>(s);
        // heads = attn @ V
        av_kernel<<<dim3(SSEQ / 64, BB * HH), 256>>>(s, kv, att);
        // x = heads@wo + bo + x
        sgemm_kernel<<<dim3(DD / 128, NT / 128), 256>>>(
            att, wo + (size_t)l * DD * DD, bo + (size_t)l * DD, x,
            x, NT, DD, DD, 2);
        // pre-FFN LN
        ln_kernel<<<NT, 256>>>(x, ffg + (size_t)l * DD, ffb + (size_t)l * DD, h);
        // f = softplus(h@w1 + b1)
        sgemm_kernel<<<dim3(FF / 128, NT / 128), 256>>>(
            h, w1 + (size_t)l * DD * FF, b1 + (size_t)l * FF, nullptr,
            f, NT, DD, FF, 1);
        // x = f@w2 + b2 + x
        sgemm_kernel<<<dim3(DD / 128, NT / 128), 256>>>(
            f, w2 + (size_t)l * FF * DD, b2 + (size_t)l * DD, x,
            x, NT, FF, DD, 2);
    }

    // final layernorm -> output
    ln_kernel<<<NT, 256>>>(x, fg, fb, (float*)d_out);
}

// round 6
// speedup vs baseline: 1.6745x; 1.6745x over previous
#include <cuda_runtime.h>
#include <cuda_bf16.h>
#include <math.h>
#include <stdint.h>

// Problem constants
#define BB 2
#define SSEQ 2048
#define DD 1024
#define HH 16
#define HD 64
#define FF 4096
#define NL 8
#define NT (BB*SSEQ)   // 4096 token rows

// ---------------- scratch (device globals: allocation-guard safe) ----------
__device__ float g_x  [NT*DD];            // residual stream fp32
__device__ float g_q  [NT*DD];            // Q fp32
__device__ float g_kv [NT*2*DD];          // K|V fp32
__device__ float g_s  [134217728];        // scores B*H*S*S (512 MB)

__device__ __nv_bfloat16 g_h_hi [NT*DD];  // LN out split
__device__ __nv_bfloat16 g_h_lo [NT*DD];
__device__ __nv_bfloat16 g_att_hi[NT*DD]; // attention heads split
__device__ __nv_bfloat16 g_att_lo[NT*DD];
__device__ __nv_bfloat16 g_f_hi [NT*FF];  // FFN hidden split
__device__ __nv_bfloat16 g_f_lo [NT*FF];

// transposed+split weights, [out][in] K-major bf16
__device__ __nv_bfloat16 g_wq_h [NL*DD*DD];
__device__ __nv_bfloat16 g_wq_l [NL*DD*DD];
__device__ __nv_bfloat16 g_wkv_h[NL*DD*2*DD];
__device__ __nv_bfloat16 g_wkv_l[NL*DD*2*DD];
__device__ __nv_bfloat16 g_wo_h [NL*DD*DD];
__device__ __nv_bfloat16 g_wo_l [NL*DD*DD];
__device__ __nv_bfloat16 g_w1_h [NL*DD*FF];
__device__ __nv_bfloat16 g_w1_l [NL*DD*FF];
__device__ __nv_bfloat16 g_w2_h [NL*FF*DD];
__device__ __nv_bfloat16 g_w2_l [NL*FF*DD];

// ---------------- small helpers --------------------------------------------
__device__ __forceinline__ float softplus_f(float x) {
    return fmaxf(x, 0.0f) + log1pf(expf(-fabsf(x)));
}
__device__ __forceinline__ uint32_t smem_u32(const void* p) {
    uint32_t a;
    asm("{ .reg .u64 t; cvta.to.shared.u64 t, %1; cvt.u32.u64 %0, t; }"
        : "=r"(a) : "l"(p));
    return a;
}
// split fp32 into hi/lo bf16 pair packed as bf16x2 words
__device__ __forceinline__ void split2(float a, float b, uint32_t& hi, uint32_t& lo) {
    __nv_bfloat162 h = __floats2bfloat162_rn(a, b);
    float ra = a - __bfloat162float(h.x);
    float rb = b - __bfloat162float(h.y);
    __nv_bfloat162 l = __floats2bfloat162_rn(ra, rb);
    hi = *(uint32_t*)&h;
    lo = *(uint32_t*)&l;
}

#define LDMX4(R0,R1,R2,R3,ADDR) \
    asm volatile("ldmatrix.sync.aligned.m8n8.x4.shared.b16 {%0,%1,%2,%3}, [%4];" \
        : "=r"(R0),"=r"(R1),"=r"(R2),"=r"(R3) : "r"(ADDR))

#define MMA16816(C, A, B0, B1) \
    asm volatile("mma.sync.aligned.m16n8k16.row.col.f32.bf16.bf16.f32 " \
        "{%0,%1,%2,%3}, {%4,%5,%6,%7}, {%8,%9}, {%0,%1,%2,%3};" \
        : "+f"((C)[0]),"+f"((C)[1]),"+f"((C)[2]),"+f"((C)[3]) \
        : "r"((A)[0]),"r"((A)[1]),"r"((A)[2]),"r"((A)[3]), "r"(B0),"r"(B1))

// ---------------- weight transpose + split: W[K,M] -> Wt_hi/lo[M,K] --------
__global__ void wconv_kernel(const float* __restrict__ W,
                             __nv_bfloat16* __restrict__ oh,
                             __nv_bfloat16* __restrict__ ol,
                             int K, int M)
{
    __shared__ float t[32][33];
    int m0 = blockIdx.x * 32, k0 = blockIdx.y * 32;
    int tx = threadIdx.x, ty = threadIdx.y;  // 32 x 8
    #pragma unroll
    for (int j = 0; j < 4; j++)
        t[ty + 8 * j][tx] = W[(size_t)(k0 + ty + 8 * j) * M + m0 + tx];
    __syncthreads();
    #pragma unroll
    for (int j = 0; j < 4; j++) {
        float v = t[tx][ty + 8 * j];
        int m = m0 + ty + 8 * j, k = k0 + tx;
        __nv_bfloat16 h = __float2bfloat16(v);
        oh[(size_t)m * K + k] = h;
        ol[(size_t)m * K + k] = __float2bfloat16(v - __bfloat162float(h));
    }
}

// ---------------- LayerNorm (fp32 out) --------------------------------------
__global__ void ln_kernel(const float* __restrict__ in,
                          const float* __restrict__ gamma,
                          const float* __restrict__ beta,
                          float* __restrict__ out)
{
    int row = blockIdx.x;
    int tid = threadIdx.x;
    const float* p = in + (size_t)row * DD;
    float4 v = *(const float4*)(p + tid * 4);
    float s  = v.x + v.y + v.z + v.w;
    float sq = v.x*v.x + v.y*v.y + v.z*v.z + v.w*v.w;
    __shared__ float sm1[8], sm2[8];
    #pragma unroll
    for (int o = 16; o > 0; o >>= 1) {
        s  += __shfl_xor_sync(0xffffffffu, s,  o);
        sq += __shfl_xor_sync(0xffffffffu, sq, o);
    }
    if ((tid & 31) == 0) { sm1[tid >> 5] = s; sm2[tid >> 5] = sq; }
    __syncthreads();
    if (tid < 32) {
        s  = (tid < 8) ? sm1[tid] : 0.0f;
        sq = (tid < 8) ? sm2[tid] : 0.0f;
        #pragma unroll
        for (int o = 4; o > 0; o >>= 1) {
            s  += __shfl_xor_sync(0xffffffffu, s,  o);
            sq += __shfl_xor_sync(0xffffffffu, sq, o);
        }
        if (tid == 0) { sm1[0] = s; sm2[0] = sq; }
    }
    __syncthreads();
    float mean = sm1[0] * (1.0f / DD);
    float var  = sm2[0] * (1.0f / DD) - mean * mean;
    float rs   = rsqrtf(var + 1e-3f);
    float4 g  = *(const float4*)(gamma + tid * 4);
    float4 be = *(const float4*)(beta  + tid * 4);
    float4 o4;
    o4.x = (v.x - mean) * rs * g.x + be.x;
    o4.y = (v.y - mean) * rs * g.y + be.y;
    o4.z = (v.z - mean) * rs * g.z + be.z;
    o4.w = (v.w - mean) * rs * g.w + be.w;
    *(float4*)(out + (size_t)row * DD + tid * 4) = o4;
}

// ---------------- LayerNorm (bf16 hi/lo out) --------------------------------
__global__ void ln_bf16_kernel(const float* __restrict__ in,
                               const float* __restrict__ gamma,
                               const float* __restrict__ beta,
                               __nv_bfloat16* __restrict__ ohi,
                               __nv_bfloat16* __restrict__ olo)
{
    int row = blockIdx.x;
    int tid = threadIdx.x;
    const float* p = in + (size_t)row * DD;
    float4 v = *(const float4*)(p + tid * 4);
    float s  = v.x + v.y + v.z + v.w;
    float sq = v.x*v.x + v.y*v.y + v.z*v.z + v.w*v.w;
    __shared__ float sm1[8], sm2[8];
    #pragma unroll
    for (int o = 16; o > 0; o >>= 1) {
        s  += __shfl_xor_sync(0xffffffffu, s,  o);
        sq += __shfl_xor_sync(0xffffffffu, sq, o);
    }
    if ((tid & 31) == 0) { sm1[tid >> 5] = s; sm2[tid >> 5] = sq; }
    __syncthreads();
    if (tid < 32) {
        s  = (tid < 8) ? sm1[tid] : 0.0f;
        sq = (tid < 8) ? sm2[tid] : 0.0f;
        #pragma unroll
        for (int o = 4; o > 0; o >>= 1) {
            s  += __shfl_xor_sync(0xffffffffu, s,  o);
            sq += __shfl_xor_sync(0xffffffffu, sq, o);
        }
        if (tid == 0) { sm1[0] = s; sm2[0] = sq; }
    }
    __syncthreads();
    float mean = sm1[0] * (1.0f / DD);
    float var  = sm2[0] * (1.0f / DD) - mean * mean;
    float rs   = rsqrtf(var + 1e-3f);
    float4 g  = *(const float4*)(gamma + tid * 4);
    float4 be = *(const float4*)(beta  + tid * 4);
    float a = (v.x - mean) * rs * g.x + be.x;
    float b = (v.y - mean) * rs * g.y + be.y;
    float c = (v.z - mean) * rs * g.z + be.z;
    float d = (v.w - mean) * rs * g.w + be.w;
    uint2 uh, ul;
    split2(a, b, uh.x, ul.x);
    split2(c, d, uh.y, ul.y);
    size_t off = (size_t)row * DD + tid * 4;
    *(uint2*)(ohi + off) = uh;
    *(uint2*)(olo + off) = ul;
}

// ---------------- HMMA split-bf16 GEMM --------------------------------------
// C[NT, M] = A[NT, K] @ B[M, K]^T (+bias, epi), K chunks of 64.
// Block: 128 rows x 64 cols, 8 warps (4m x 2n), warp tile 32x32.
// epi: 0 = bias -> fp32 ; 1 = bias+softplus -> bf16 hi/lo ; 2 = bias+res -> fp32
#define TSTR 72                      // smem row stride in bf16 elems (144 B)
#define SA_H 0
#define SA_L (128*TSTR*2)            // 18432
#define SB_H (2*128*TSTR*2)          // 36864
#define SB_L (SB_H + 64*TSTR*2)      // 46080
#define TG_SMEM (SB_L + 64*TSTR*2)   // 55296

__global__ void __launch_bounds__(256) tgemm_kernel(
    const __nv_bfloat16* __restrict__ Ah, const __nv_bfloat16* __restrict__ Al,
    const __nv_bfloat16* __restrict__ Bh, const __nv_bfloat16* __restrict__ Bl,
    const float* __restrict__ bias, const float* __restrict__ res,
    float* __restrict__ C, __nv_bfloat16* __restrict__ Chi,
    __nv_bfloat16* __restrict__ Clo, int K, int M, int epi)
{
    extern __shared__ char smem[];
    uint32_t sb = smem_u32(smem);
    int tid  = threadIdx.x;
    int lane = tid & 31;
    int w    = tid >> 5;
    int wm   = w & 3;            // 0..3 -> 32-row group
    int wn   = w >> 2;           // 0..1 -> 32-col group

    int m0 = blockIdx.y * 128;
    int n0 = blockIdx.x * 64;

    float acc[2][4][4];
    #pragma unroll
    for (int i = 0; i < 2; i++)
        #pragma unroll
        for (int j = 0; j < 4; j++)
            #pragma unroll
            for (int c = 0; c < 4; c++) acc[i][j][c] = 0.0f;

    // ldmatrix smem byte offsets (within tile), per-thread
    // A frags: row = wm*32 + i*16 + (lane&15), col = k0 + ((lane>>4)<<3)
    uint32_t a_off = (uint32_t)((wm * 32 + (lane & 15)) * TSTR + ((lane >> 4) << 3)) * 2;
    // B frags: row = wn*32 + p*16 + ((lane>>4)<<3) + (lane&7), col = k0 + (((lane>>3)&1)<<3)
    uint32_t b_off = (uint32_t)((wn * 32 + ((lane >> 4) << 3) + (lane & 7)) * TSTR
                                + (((lane >> 3) & 1) << 3)) * 2;

    int nch = K >> 6;
    for (int kc = 0; kc < nch; kc++) {
        int kbase = kc * 64;
        // ---- load A tiles (128x64) hi+lo : 1024 uint4 each ----
        #pragma unroll
        for (int u = 0; u < 4; u++) {
            int idx = tid + u * 256;
            int r = idx >> 3, c = idx & 7;
            size_t g = (size_t)(m0 + r) * K + kbase + c * 8;
            uint32_t so = (uint32_t)(r * TSTR + c * 8) * 2;
            *(uint4*)(smem + SA_H + so) = *(const uint4*)(Ah + g);
            *(uint4*)(smem + SA_L + so) = *(const uint4*)(Al + g);
        }
        // ---- load B tiles (64x64) hi+lo : 512 uint4 each ----
        #pragma unroll
        for (int u = 0; u < 2; u++) {
            int idx = tid + u * 256;
            int r = idx >> 3, c = idx & 7;
            size_t g = (size_t)(n0 + r) * K + kbase + c * 8;
            uint32_t so = (uint32_t)(r * TSTR + c * 8) * 2;
            *(uint4*)(smem + SB_H + so) = *(const uint4*)(Bh + g);
            *(uint4*)(smem + SB_L + so) = *(const uint4*)(Bl + g);
        }
        __syncthreads();

        #pragma unroll
        for (int ks = 0; ks < 4; ks++) {
            uint32_t kb = (uint32_t)(ks * 16) * 2;    // byte offset in k
            uint32_t ah[2][4], al[2][4], bh[2][4], bl[2][4];
            #pragma unroll
            for (int i = 0; i < 2; i++) {
                uint32_t aa = sb + SA_H + a_off + (uint32_t)(i * 16 * TSTR) * 2 + kb;
                LDMX4(ah[i][0], ah[i][1], ah[i][2], ah[i][3], aa);
                uint32_t aa2 = sb + SA_L + a_off + (uint32_t)(i * 16 * TSTR) * 2 + kb;
                LDMX4(al[i][0], al[i][1], al[i][2], al[i][3], aa2);
            }
            #pragma unroll
            for (int p = 0; p < 2; p++) {
                uint32_t ba = sb + SB_H + b_off + (uint32_t)(p * 16 * TSTR) * 2 + kb;
                LDMX4(bh[p][0], bh[p][1], bh[p][2], bh[p][3], ba);
                uint32_t ba2 = sb + SB_L + b_off + (uint32_t)(p * 16 * TSTR) * 2 + kb;
                LDMX4(bl[p][0], bl[p][1], bl[p][2], bl[p][3], ba2);
            }
            #pragma unroll
            for (int i = 0; i < 2; i++)
                #pragma unroll
                for (int p = 0; p < 2; p++)
                    #pragma unroll
                    for (int sub = 0; sub < 2; sub++) {
                        int j = p * 2 + sub;
                        MMA16816(acc[i][j], ah[i], bh[p][sub * 2], bh[p][sub * 2 + 1]);
                        MMA16816(acc[i][j], ah[i], bl[p][sub * 2], bl[p][sub * 2 + 1]);
                        MMA16816(acc[i][j], al[i], bh[p][sub * 2], bh[p][sub * 2 + 1]);
                    }
        }
        __syncthreads();
    }

    // ---- epilogue ----
    #pragma unroll
    for (int i = 0; i < 2; i++) {
        int row0 = m0 + wm * 32 + i * 16 + (lane >> 2);
        #pragma unroll
        for (int j = 0; j < 4; j++) {
            int pp = j >> 1, sub = j & 1;
            int col = n0 + wn * 32 + pp * 16 + sub * 8 + (lane & 3) * 2;
            float2 b2 = *(const float2*)(bias + col);
            #pragma unroll
            for (int half = 0; half < 2; half++) {
                int r = row0 + half * 8;
                float o0 = acc[i][j][half * 2 + 0] + b2.x;
                float o1 = acc[i][j][half * 2 + 1] + b2.y;
                size_t off = (size_t)r * M + col;
                if (epi == 1) {
                    o0 = softplus_f(o0); o1 = softplus_f(o1);
                    uint32_t uh, ul;
                    split2(o0, o1, uh, ul);
                    *(uint32_t*)(Chi + off) = uh;
                    *(uint32_t*)(Clo + off) = ul;
                } else {
                    if (epi == 2) {
                        float2 r2 = *(const float2*)(res + off);
                        o0 += r2.x; o1 += r2.y;
                    }
                    float2 o = {o0, o1};
                    *(float2*)(C + off) = o;
                }
            }
        }
    }
}

// ---------------- attention scores (FFMA, causal skip) ----------------------
__global__ void __launch_bounds__(256) score_kernel(
    const float* __restrict__ q, const float* __restrict__ kv,
    float* __restrict__ sc)
{
    int kt = blockIdx.x, qt = blockIdx.y, bh = blockIdx.z;
    if (kt > qt) return;
    int b = bh >> 4, h = bh & 15;

    __shared__ float Qs[64][68];
    __shared__ float Ks[64][68];
    int tid = threadIdx.x;
    int r0 = tid >> 4;
    int d0 = (tid & 15) * 4;
    int tx = tid & 15, ty = tid >> 4;

    const float* qbase = q  + (size_t)b * SSEQ * DD       + h * HD;
    const float* kbase = kv + (size_t)b * SSEQ * (2 * DD) + h * HD;

    #pragma unroll
    for (int i = 0; i < 4; i++) {
        int row = r0 + i * 16;
        float4 qa = *(const float4*)(qbase + (size_t)(qt * 64 + row) * DD + d0);
        Qs[d0 + 0][row] = qa.x; Qs[d0 + 1][row] = qa.y;
        Qs[d0 + 2][row] = qa.z; Qs[d0 + 3][row] = qa.w;
        float4 ka = *(const float4*)(kbase + (size_t)(kt * 64 + row) * (2 * DD) + d0);
        Ks[d0 + 0][row] = ka.x; Ks[d0 + 1][row] = ka.y;
        Ks[d0 + 2][row] = ka.z; Ks[d0 + 3][row] = ka.w;
    }
    __syncthreads();

    float acc[4][4];
    #pragma unroll
    for (int i = 0; i < 4; i++)
        #pragma unroll
        for (int j = 0; j < 4; j++) acc[i][j] = 0.0f;

    #pragma unroll 16
    for (int kk = 0; kk < 64; kk++) {
        float4 a = *(const float4*)&Qs[kk][ty * 4];
        float4 c = *(const float4*)&Ks[kk][tx * 4];
        float ar[4] = {a.x, a.y, a.z, a.w};
        float cr[4] = {c.x, c.y, c.z, c.w};
        #pragma unroll
        for (int i = 0; i < 4; i++)
            #pragma unroll
            for (int j = 0; j < 4; j++)
                acc[i][j] += ar[i] * cr[j];
    }

    float slope = exp2f(-0.5f * (float)(h + 1));
    #pragma unroll
    for (int i = 0; i < 4; i++) {
        int qrow = qt * 64 + ty * 4 + i;
        float* out = sc + ((size_t)bh * SSEQ + qrow) * SSEQ + kt * 64 + tx * 4;
        float4 o;
        int k0 = kt * 64 + tx * 4;
        o.x = acc[i][0] * 0.125f + slope * (float)(k0 + 0 - qrow);
        o.y = acc[i][1] * 0.125f + slope * (float)(k0 + 1 - qrow);
        o.z = acc[i][2] * 0.125f + slope * (float)(k0 + 2 - qrow);
        o.w = acc[i][3] * 0.125f + slope * (float)(k0 + 3 - qrow);
        *(float4*)out = o;
    }
}

// ---------------- causal softmax --------------------------------------------
__global__ void __launch_bounds__(256) softmax_kernel(float* __restrict__ sc)
{
    int qrow = blockIdx.x;
    int bh   = blockIdx.y;
    float* row = sc + ((size_t)bh * SSEQ + qrow) * SSEQ;
    int tid  = threadIdx.x;
    int Lpad = ((qrow >> 6) + 1) << 6;

    float4 v[2];
    int k0s[2];
    float mx = -1e30f;
    #pragma unroll
    for (int c = 0; c < 2; c++) {
        int k0 = (tid + c * 256) * 4;
        k0s[c] = k0;
        if (k0 < Lpad) {
            float4 t = *(float4*)(row + k0);
            t.x = (k0 + 0 <= qrow) ? t.x : -1e30f;
            t.y = (k0 + 1 <= qrow) ? t.y : -1e30f;
            t.z = (k0 + 2 <= qrow) ? t.z : -1e30f;
            t.w = (k0 + 3 <= qrow) ? t.w : -1e30f;
            v[c] = t;
            mx = fmaxf(mx, fmaxf(fmaxf(t.x, t.y), fmaxf(t.z, t.w)));
        }
    }

    __shared__ float sm[8];
    #pragma unroll
    for (int o = 16; o > 0; o >>= 1) mx = fmaxf(mx, __shfl_xor_sync(0xffffffffu, mx, o));
    if ((tid & 31) == 0) sm[tid >> 5] = mx;
    __syncthreads();
    if (tid < 32) {
        mx = (tid < 8) ? sm[tid] : -1e30f;
        #pragma unroll
        for (int o = 4; o > 0; o >>= 1) mx = fmaxf(mx, __shfl_xor_sync(0xffffffffu, mx, o));
        if (tid == 0) sm[0] = mx;
    }
    __syncthreads();
    mx = sm[0];
    __syncthreads();

    float s = 0.0f;
    #pragma unroll
    for (int c = 0; c < 2; c++) {
        if (k0s[c] < Lpad) {
            v[c].x = expf(v[c].x - mx);
            v[c].y = expf(v[c].y - mx);
            v[c].z = expf(v[c].z - mx);
            v[c].w = expf(v[c].w - mx);
            s += v[c].x + v[c].y + v[c].z + v[c].w;
        }
    }
    #pragma unroll
    for (int o = 16; o > 0; o >>= 1) s += __shfl_xor_sync(0xffffffffu, s, o);
    if ((tid & 31) == 0) sm[tid >> 5] = s;
    __syncthreads();
    if (tid < 32) {
        s = (tid < 8) ? sm[tid] : 0.0f;
        #pragma unroll
        for (int o = 4; o > 0; o >>= 1) s += __shfl_xor_sync(0xffffffffu, s, o);
        if (tid == 0) sm[0] = s;
    }
    __syncthreads();
    float inv = 1.0f / sm[0];

    #pragma unroll
    for (int c = 0; c < 2; c++) {
        if (k0s[c] < Lpad) {
            float4 t = v[c];
            t.x *= inv; t.y *= inv; t.z *= inv; t.w *= inv;
            *(float4*)(row + k0s[c]) = t;
        }
    }
}

// ---------------- A.V (FFMA, causal) -> bf16 hi/lo ---------------------------
__global__ void __launch_bounds__(256) av_kernel(
    const float* __restrict__ sc, const float* __restrict__ kv,
    __nv_bfloat16* __restrict__ ohi, __nv_bfloat16* __restrict__ olo)
{
    int qt = blockIdx.x;
    int bh = blockIdx.y;
    int b = bh >> 4, h = bh & 15;

    __shared__ float As[64][68];
    __shared__ float Vs[64][68];
    int tid = threadIdx.x;
    int r0 = tid >> 4;
    int d0 = (tid & 15) * 4;
    int tx = tid & 15, ty = tid >> 4;

    const float* abase = sc + ((size_t)bh * SSEQ + qt * 64) * SSEQ;
    const float* vbase = kv + (size_t)b * SSEQ * (2 * DD) + DD + h * HD;

    float acc[4][4];
    #pragma unroll
    for (int i = 0; i < 4; i++)
        #pragma unroll
        for (int j = 0; j < 4; j++) acc[i][j] = 0.0f;

    for (int kt = 0; kt <= qt; kt++) {
        #pragma unroll
        for (int i = 0; i < 4; i++) {
            int row = r0 + i * 16;
            float4 a = *(const float4*)(abase + (size_t)row * SSEQ + kt * 64 + d0);
            As[d0 + 0][row] = a.x; As[d0 + 1][row] = a.y;
            As[d0 + 2][row] = a.z; As[d0 + 3][row] = a.w;
            float4 vv = *(const float4*)(vbase + (size_t)(kt * 64 + row) * (2 * DD) + d0);
            *(float4*)&Vs[row][d0] = vv;
        }
        __syncthreads();
        #pragma unroll 16
        for (int kk = 0; kk < 64; kk++) {
            float4 a = *(const float4*)&As[kk][ty * 4];
            float4 vv = *(const float4*)&Vs[kk][tx * 4];
            float ar[4] = {a.x, a.y, a.z, a.w};
            float vr[4] = {vv.x, vv.y, vv.z, vv.w};
            #pragma unroll
            for (int i = 0; i < 4; i++)
                #pragma unroll
                for (int j = 0; j < 4; j++)
                    acc[i][j] += ar[i] * vr[j];
        }
        __syncthreads();
    }

    #pragma unroll
    for (int i = 0; i < 4; i++) {
        int qrow = qt * 64 + ty * 4 + i;
        uint2 uh, ul;
        split2(acc[i][0], acc[i][1], uh.x, ul.x);
        split2(acc[i][2], acc[i][3], uh.y, ul.y);
        size_t off = ((size_t)b * SSEQ + qrow) * DD + h * HD + tx * 4;
        *(uint2*)(ohi + off) = uh;
        *(uint2*)(olo + off) = ul;
    }
}

// ---------------- host orchestration ---------------------------------------
extern "C" void kernel_launch(void* const* d_in, const int* in_sizes, int n_in,
                              void* d_out, int out_size)
{
    const float *ts, *fg, *fb, *wq, *bq, *wkv, *bkv, *wo, *bo,
                *w1, *b1, *w2, *b2, *ag, *ab, *ffg, *ffb;
    if (in_sizes[1] == 1024) {
        ts  = (const float*)d_in[0];
        fg  = (const float*)d_in[1];  fb  = (const float*)d_in[2];
        wq  = (const float*)d_in[3];  bq  = (const float*)d_in[4];
        wkv = (const float*)d_in[5];  bkv = (const float*)d_in[6];
        wo  = (const float*)d_in[7];  bo  = (const float*)d_in[8];
        w1  = (const float*)d_in[9];  b1  = (const float*)d_in[10];
        w2  = (const float*)d_in[11]; b2  = (const float*)d_in[12];
        ag  = (const float*)d_in[13]; ab  = (const float*)d_in[14];
        ffg = (const float*)d_in[15]; ffb = (const float*)d_in[16];
    } else {
        ts  = (const float*)d_in[0];
        wq  = (const float*)d_in[1];  bq  = (const float*)d_in[2];
        wkv = (const float*)d_in[3];  bkv = (const float*)d_in[4];
        wo  = (const float*)d_in[5];  bo  = (const float*)d_in[6];
        w1  = (const float*)d_in[7];  b1  = (const float*)d_in[8];
        w2  = (const float*)d_in[9];  b2  = (const float*)d_in[10];
        ag  = (const float*)d_in[11]; ab  = (const float*)d_in[12];
        ffg = (const float*)d_in[13]; ffb = (const float*)d_in[14];
        fg  = (const float*)d_in[15]; fb  = (const float*)d_in[16];
    }

    float *x, *q, *kv, *s;
    __nv_bfloat16 *hh, *hl, *ath, *atl, *fh, *fl;
    __nv_bfloat16 *wqh, *wql, *wkvh, *wkvl, *woh, *wol, *w1h, *w1l, *w2h, *w2l;
    cudaGetSymbolAddress((void**)&x,   g_x);
    cudaGetSymbolAddress((void**)&q,   g_q);
    cudaGetSymbolAddress((void**)&kv,  g_kv);
    cudaGetSymbolAddress((void**)&s,   g_s);
    cudaGetSymbolAddress((void**)&hh,  g_h_hi);
    cudaGetSymbolAddress((void**)&hl,  g_h_lo);
    cudaGetSymbolAddress((void**)&ath, g_att_hi);
    cudaGetSymbolAddress((void**)&atl, g_att_lo);
    cudaGetSymbolAddress((void**)&fh,  g_f_hi);
    cudaGetSymbolAddress((void**)&fl,  g_f_lo);
    cudaGetSymbolAddress((void**)&wqh,  g_wq_h);
    cudaGetSymbolAddress((void**)&wql,  g_wq_l);
    cudaGetSymbolAddress((void**)&wkvh, g_wkv_h);
    cudaGetSymbolAddress((void**)&wkvl, g_wkv_l);
    cudaGetSymbolAddress((void**)&woh,  g_wo_h);
    cudaGetSymbolAddress((void**)&wol,  g_wo_l);
    cudaGetSymbolAddress((void**)&w1h,  g_w1_h);
    cudaGetSymbolAddress((void**)&w1l,  g_w1_l);
    cudaGetSymbolAddress((void**)&w2h,  g_w2_h);
    cudaGetSymbolAddress((void**)&w2l,  g_w2_l);

    cudaFuncSetAttribute(tgemm_kernel,
                         cudaFuncAttributeMaxDynamicSharedMemorySize, TG_SMEM);

    cudaMemcpyAsync(x, ts, sizeof(float) * (size_t)NT * DD,
                    cudaMemcpyDeviceToDevice, 0);

    // weight transpose + split (per layer)
    for (int l = 0; l < NL; l++) {
        dim3 blk(32, 8);
        wconv_kernel<<<dim3(DD/32, DD/32), blk>>>(
            wq + (size_t)l*DD*DD, wqh + (size_t)l*DD*DD, wql + (size_t)l*DD*DD, DD, DD);
        wconv_kernel<<<dim3(2*DD/32, DD/32), blk>>>(
            wkv + (size_t)l*DD*2*DD, wkvh + (size_t)l*DD*2*DD, wkvl + (size_t)l*DD*2*DD, DD, 2*DD);
        wconv_kernel<<<dim3(DD/32, DD/32), blk>>>(
            wo + (size_t)l*DD*DD, woh + (size_t)l*DD*DD, wol + (size_t)l*DD*DD, DD, DD);
        wconv_kernel<<<dim3(FF/32, DD/32), blk>>>(
            w1 + (size_t)l*DD*FF, w1h + (size_t)l*DD*FF, w1l + (size_t)l*DD*FF, DD, FF);
        wconv_kernel<<<dim3(DD/32, FF/32), blk>>>(
            w2 + (size_t)l*FF*DD, w2h + (size_t)l*FF*DD, w2l + (size_t)l*FF*DD, FF, DD);
    }

    for (int l = 0; l < NL; l++) {
        // pre-attention LN -> bf16 split
        ln_bf16_kernel<<<NT, 256>>>(x, ag + (size_t)l*DD, ab + (size_t)l*DD, hh, hl);
        // Q = h@wq + bq (fp32 out)
        tgemm_kernel<<<dim3(DD/64, NT/128), 256, TG_SMEM>>>(
            hh, hl, wqh + (size_t)l*DD*DD, wql + (size_t)l*DD*DD,
            bq + (size_t)l*DD, nullptr, q, nullptr, nullptr, DD, DD, 0);
        // KV = h@wkv + bkv (fp32 out)
        tgemm_kernel<<<dim3(2*DD/64, NT/128), 256, TG_SMEM>>>(
            hh, hl, wkvh + (size_t)l*DD*2*DD, wkvl + (size_t)l*DD*2*DD,
            bkv + (size_t)l*2*DD, nullptr, kv, nullptr, nullptr, DD, 2*DD, 0);
        // attention
        score_kernel<<<dim3(SSEQ/64, SSEQ/64, BB*HH), 256>>>(q, kv, s);
        softmax_kernel<<<dim3(SSEQ, BB*HH), 256>>>(s);
        av_kernel<<<dim3(SSEQ/64, BB*HH), 256>>>(s, kv, ath, atl);
        // x = heads@wo + bo + x
        tgemm_kernel<<<dim3(DD/64, NT/128), 256, TG_SMEM>>>(
            ath, atl, woh + (size_t)l*DD*DD, wol + (size_t)l*DD*DD,
            bo + (size_t)l*DD, x, x, nullptr, nullptr, DD, DD, 2);
        // pre-FFN LN -> bf16 split
        ln_bf16_kernel<<<NT, 256>>>(x, ffg + (size_t)l*DD, ffb + (size_t)l*DD, hh, hl);
        // f = softplus(h@w1 + b1) -> bf16 split
        tgemm_kernel<<<dim3(FF/64, NT/128), 256, TG_SMEM>>>(
            hh, hl, w1h + (size_t)l*DD*FF, w1l + (size_t)l*DD*FF,
            b1 + (size_t)l*FF, nullptr, nullptr, fh, fl, DD, FF, 1);
        // x = f@w2 + b2 + x
        tgemm_kernel<<<dim3(DD/64, NT/128), 256, TG_SMEM>>>(
            fh, fl, w2h + (size_t)l*FF*DD, w2l + (size_t)l*FF*DD,
            b2 + (size_t)l*DD, x, x, nullptr, nullptr, FF, DD, 2);
    }

    // final layernorm -> output (fp32)
    ln_kernel<<<NT, 256>>>(x, fg, fb, (float*)d_out);
}

// round 7
// speedup vs baseline: 2.3932x; 1.4292x over previous
#include <cuda_runtime.h>
#include <cuda_bf16.h>
#include <math.h>
#include <stdint.h>

// Problem constants
#define BB 2
#define SSEQ 2048
#define DD 1024
#define HH 16
#define HD 64
#define FF 4096
#define NL 8
#define NT (BB*SSEQ)   // 4096 token rows

// ---------------- scratch (device globals: allocation-guard safe) ----------
__device__ float g_x  [NT*DD];            // residual stream fp32

__device__ __nv_bfloat16 g_h_hi [NT*DD];  // LN out split
__device__ __nv_bfloat16 g_h_lo [NT*DD];
__device__ __nv_bfloat16 g_q_hi [NT*DD];  // Q split (pre-scaled by 1/8)
__device__ __nv_bfloat16 g_q_lo [NT*DD];
__device__ __nv_bfloat16 g_kv_hi[NT*2*DD];// K|V split
__device__ __nv_bfloat16 g_kv_lo[NT*2*DD];
__device__ __nv_bfloat16 g_att_hi[NT*DD]; // attention heads split
__device__ __nv_bfloat16 g_att_lo[NT*DD];
__device__ __nv_bfloat16 g_f_hi [NT*FF];  // FFN hidden split
__device__ __nv_bfloat16 g_f_lo [NT*FF];

// transposed+split weights, [out][in] K-major bf16
__device__ __nv_bfloat16 g_wq_h [NL*DD*DD];
__device__ __nv_bfloat16 g_wq_l [NL*DD*DD];
__device__ __nv_bfloat16 g_wkv_h[NL*DD*2*DD];
__device__ __nv_bfloat16 g_wkv_l[NL*DD*2*DD];
__device__ __nv_bfloat16 g_wo_h [NL*DD*DD];
__device__ __nv_bfloat16 g_wo_l [NL*DD*DD];
__device__ __nv_bfloat16 g_w1_h [NL*DD*FF];
__device__ __nv_bfloat16 g_w1_l [NL*DD*FF];
__device__ __nv_bfloat16 g_w2_h [NL*FF*DD];
__device__ __nv_bfloat16 g_w2_l [NL*FF*DD];

// ---------------- small helpers --------------------------------------------
__device__ __forceinline__ float softplus_f(float x) {
    return fmaxf(x, 0.0f) + log1pf(expf(-fabsf(x)));
}
__device__ __forceinline__ uint32_t smem_u32(const void* p) {
    uint32_t a;
    asm("{ .reg .u64 t; cvta.to.shared.u64 t, %1; cvt.u32.u64 %0, t; }"
        : "=r"(a) : "l"(p));
    return a;
}
// split fp32 into hi/lo bf16 pair packed as bf16x2 words
__device__ __forceinline__ void split2(float a, float b, uint32_t& hi, uint32_t& lo) {
    __nv_bfloat162 h = __floats2bfloat162_rn(a, b);
    float ra = a - __bfloat162float(h.x);
    float rb = b - __bfloat162float(h.y);
    __nv_bfloat162 l = __floats2bfloat162_rn(ra, rb);
    hi = *(uint32_t*)&h;
    lo = *(uint32_t*)&l;
}

#define LDMX4(R0,R1,R2,R3,ADDR) \
    asm volatile("ldmatrix.sync.aligned.m8n8.x4.shared.b16 {%0,%1,%2,%3}, [%4];" \
        : "=r"(R0),"=r"(R1),"=r"(R2),"=r"(R3) : "r"(ADDR))

#define LDMX4T(R0,R1,R2,R3,ADDR) \
    asm volatile("ldmatrix.sync.aligned.m8n8.x4.trans.shared.b16 {%0,%1,%2,%3}, [%4];" \
        : "=r"(R0),"=r"(R1),"=r"(R2),"=r"(R3) : "r"(ADDR))

#define MMA16816(C, A, B0, B1) \
    asm volatile("mma.sync.aligned.m16n8k16.row.col.f32.bf16.bf16.f32 " \
        "{%0,%1,%2,%3}, {%4,%5,%6,%7}, {%8,%9}, {%0,%1,%2,%3};" \
        : "+f"((C)[0]),"+f"((C)[1]),"+f"((C)[2]),"+f"((C)[3]) \
        : "r"((A)[0]),"r"((A)[1]),"r"((A)[2]),"r"((A)[3]), "r"(B0),"r"(B1))

// ---------------- weight transpose + split: W[K,M] -> Wt_hi/lo[M,K] --------
__global__ void wconv_kernel(const float* __restrict__ W,
                             __nv_bfloat16* __restrict__ oh,
                             __nv_bfloat16* __restrict__ ol,
                             int K, int M)
{
    __shared__ float t[32][33];
    int m0 = blockIdx.x * 32, k0 = blockIdx.y * 32;
    int tx = threadIdx.x, ty = threadIdx.y;  // 32 x 8
    #pragma unroll
    for (int j = 0; j < 4; j++)
        t[ty + 8 * j][tx] = W[(size_t)(k0 + ty + 8 * j) * M + m0 + tx];
    __syncthreads();
    #pragma unroll
    for (int j = 0; j < 4; j++) {
        float v = t[tx][ty + 8 * j];
        int m = m0 + ty + 8 * j, k = k0 + tx;
        __nv_bfloat16 h = __float2bfloat16(v);
        oh[(size_t)m * K + k] = h;
        ol[(size_t)m * K + k] = __float2bfloat16(v - __bfloat162float(h));
    }
}

// ---------------- LayerNorm (fp32 out) --------------------------------------
__global__ void ln_kernel(const float* __restrict__ in,
                          const float* __restrict__ gamma,
                          const float* __restrict__ beta,
                          float* __restrict__ out)
{
    int row = blockIdx.x;
    int tid = threadIdx.x;
    const float* p = in + (size_t)row * DD;
    float4 v = *(const float4*)(p + tid * 4);
    float s  = v.x + v.y + v.z + v.w;
    float sq = v.x*v.x + v.y*v.y + v.z*v.z + v.w*v.w;
    __shared__ float sm1[8], sm2[8];
    #pragma unroll
    for (int o = 16; o > 0; o >>= 1) {
        s  += __shfl_xor_sync(0xffffffffu, s,  o);
        sq += __shfl_xor_sync(0xffffffffu, sq, o);
    }
    if ((tid & 31) == 0) { sm1[tid >> 5] = s; sm2[tid >> 5] = sq; }
    __syncthreads();
    if (tid < 32) {
        s  = (tid < 8) ? sm1[tid] : 0.0f;
        sq = (tid < 8) ? sm2[tid] : 0.0f;
        #pragma unroll
        for (int o = 4; o > 0; o >>= 1) {
            s  += __shfl_xor_sync(0xffffffffu, s,  o);
            sq += __shfl_xor_sync(0xffffffffu, sq, o);
        }
        if (tid == 0) { sm1[0] = s; sm2[0] = sq; }
    }
    __syncthreads();
    float mean = sm1[0] * (1.0f / DD);
    float var  = sm2[0] * (1.0f / DD) - mean * mean;
    float rs   = rsqrtf(var + 1e-3f);
    float4 g  = *(const float4*)(gamma + tid * 4);
    float4 be = *(const float4*)(beta  + tid * 4);
    float4 o4;
    o4.x = (v.x - mean) * rs * g.x + be.x;
    o4.y = (v.y - mean) * rs * g.y + be.y;
    o4.z = (v.z - mean) * rs * g.z + be.z;
    o4.w = (v.w - mean) * rs * g.w + be.w;
    *(float4*)(out + (size_t)row * DD + tid * 4) = o4;
}

// ---------------- LayerNorm (bf16 hi/lo out) --------------------------------
__global__ void ln_bf16_kernel(const float* __restrict__ in,
                               const float* __restrict__ gamma,
                               const float* __restrict__ beta,
                               __nv_bfloat16* __restrict__ ohi,
                               __nv_bfloat16* __restrict__ olo)
{
    int row = blockIdx.x;
    int tid = threadIdx.x;
    const float* p = in + (size_t)row * DD;
    float4 v = *(const float4*)(p + tid * 4);
    float s  = v.x + v.y + v.z + v.w;
    float sq = v.x*v.x + v.y*v.y + v.z*v.z + v.w*v.w;
    __shared__ float sm1[8], sm2[8];
    #pragma unroll
    for (int o = 16; o > 0; o >>= 1) {
        s  += __shfl_xor_sync(0xffffffffu, s,  o);
        sq += __shfl_xor_sync(0xffffffffu, sq, o);
    }
    if ((tid & 31) == 0) { sm1[tid >> 5] = s; sm2[tid >> 5] = sq; }
    __syncthreads();
    if (tid < 32) {
        s  = (tid < 8) ? sm1[tid] : 0.0f;
        sq = (tid < 8) ? sm2[tid] : 0.0f;
        #pragma unroll
        for (int o = 4; o > 0; o >>= 1) {
            s  += __shfl_xor_sync(0xffffffffu, s,  o);
            sq += __shfl_xor_sync(0xffffffffu, sq, o);
        }
        if (tid == 0) { sm1[0] = s; sm2[0] = sq; }
    }
    __syncthreads();
    float mean = sm1[0] * (1.0f / DD);
    float var  = sm2[0] * (1.0f / DD) - mean * mean;
    float rs   = rsqrtf(var + 1e-3f);
    float4 g  = *(const float4*)(gamma + tid * 4);
    float4 be = *(const float4*)(beta  + tid * 4);
    float a = (v.x - mean) * rs * g.x + be.x;
    float b = (v.y - mean) * rs * g.y + be.y;
    float c = (v.z - mean) * rs * g.z + be.z;
    float d = (v.w - mean) * rs * g.w + be.w;
    uint2 uh, ul;
    split2(a, b, uh.x, ul.x);
    split2(c, d, uh.y, ul.y);
    size_t off = (size_t)row * DD + tid * 4;
    *(uint2*)(ohi + off) = uh;
    *(uint2*)(olo + off) = ul;
}

// ---------------- HMMA split-bf16 GEMM --------------------------------------
// C[NT, M] = A[NT, K] @ B[M, K]^T (+bias), K chunks of 64.
// Block: 128 rows x 64 cols, 8 warps (4m x 2n), warp tile 32x32.
// epi: 0 = bias -> fp32 ; 1 = bias+softplus -> bf16 hi/lo ;
//      2 = bias+res -> fp32 ; 3 = (bias)*scale -> bf16 hi/lo
#define TSTR 72                      // smem row stride in bf16 elems (144 B)
#define SA_H 0
#define SA_L (128*TSTR*2)            // 18432
#define SB_H (2*128*TSTR*2)          // 36864
#define SB_L (SB_H + 64*TSTR*2)      // 46080
#define TG_SMEM (SB_L + 64*TSTR*2)   // 55296

__global__ void __launch_bounds__(256) tgemm_kernel(
    const __nv_bfloat16* __restrict__ Ah, const __nv_bfloat16* __restrict__ Al,
    const __nv_bfloat16* __restrict__ Bh, const __nv_bfloat16* __restrict__ Bl,
    const float* __restrict__ bias, const float* __restrict__ res,
    float* __restrict__ C, __nv_bfloat16* __restrict__ Chi,
    __nv_bfloat16* __restrict__ Clo, int K, int M, int epi, float scale)
{
    extern __shared__ char smem[];
    uint32_t sb = smem_u32(smem);
    int tid  = threadIdx.x;
    int lane = tid & 31;
    int w    = tid >> 5;
    int wm   = w & 3;            // 0..3 -> 32-row group
    int wn   = w >> 2;           // 0..1 -> 32-col group

    int m0 = blockIdx.y * 128;
    int n0 = blockIdx.x * 64;

    float acc[2][4][4];
    #pragma unroll
    for (int i = 0; i < 2; i++)
        #pragma unroll
        for (int j = 0; j < 4; j++)
            #pragma unroll
            for (int c = 0; c < 4; c++) acc[i][j][c] = 0.0f;

    uint32_t a_off = (uint32_t)((wm * 32 + (lane & 15)) * TSTR + ((lane >> 4) << 3)) * 2;
    uint32_t b_off = (uint32_t)((wn * 32 + ((lane >> 4) << 3) + (lane & 7)) * TSTR
                                + (((lane >> 3) & 1) << 3)) * 2;

    int nch = K >> 6;
    for (int kc = 0; kc < nch; kc++) {
        int kbase = kc * 64;
        #pragma unroll
        for (int u = 0; u < 4; u++) {
            int idx = tid + u * 256;
            int r = idx >> 3, c = idx & 7;
            size_t g = (size_t)(m0 + r) * K + kbase + c * 8;
            uint32_t so = (uint32_t)(r * TSTR + c * 8) * 2;
            *(uint4*)(smem + SA_H + so) = *(const uint4*)(Ah + g);
            *(uint4*)(smem + SA_L + so) = *(const uint4*)(Al + g);
        }
        #pragma unroll
        for (int u = 0; u < 2; u++) {
            int idx = tid + u * 256;
            int r = idx >> 3, c = idx & 7;
            size_t g = (size_t)(n0 + r) * K + kbase + c * 8;
            uint32_t so = (uint32_t)(r * TSTR + c * 8) * 2;
            *(uint4*)(smem + SB_H + so) = *(const uint4*)(Bh + g);
            *(uint4*)(smem + SB_L + so) = *(const uint4*)(Bl + g);
        }
        __syncthreads();

        #pragma unroll
        for (int ks = 0; ks < 4; ks++) {
            uint32_t kb = (uint32_t)(ks * 16) * 2;
            uint32_t ah[2][4], al[2][4], bh[2][4], bl[2][4];
            #pragma unroll
            for (int i = 0; i < 2; i++) {
                uint32_t aa = sb + SA_H + a_off + (uint32_t)(i * 16 * TSTR) * 2 + kb;
                LDMX4(ah[i][0], ah[i][1], ah[i][2], ah[i][3], aa);
                uint32_t aa2 = sb + SA_L + a_off + (uint32_t)(i * 16 * TSTR) * 2 + kb;
                LDMX4(al[i][0], al[i][1], al[i][2], al[i][3], aa2);
            }
            #pragma unroll
            for (int p = 0; p < 2; p++) {
                uint32_t ba = sb + SB_H + b_off + (uint32_t)(p * 16 * TSTR) * 2 + kb;
                LDMX4(bh[p][0], bh[p][1], bh[p][2], bh[p][3], ba);
                uint32_t ba2 = sb + SB_L + b_off + (uint32_t)(p * 16 * TSTR) * 2 + kb;
                LDMX4(bl[p][0], bl[p][1], bl[p][2], bl[p][3], ba2);
            }
            #pragma unroll
            for (int i = 0; i < 2; i++)
                #pragma unroll
                for (int p = 0; p < 2; p++)
                    #pragma unroll
                    for (int sub = 0; sub < 2; sub++) {
                        int j = p * 2 + sub;
                        MMA16816(acc[i][j], ah[i], bh[p][sub * 2], bh[p][sub * 2 + 1]);
                        MMA16816(acc[i][j], ah[i], bl[p][sub * 2], bl[p][sub * 2 + 1]);
                        MMA16816(acc[i][j], al[i], bh[p][sub * 2], bh[p][sub * 2 + 1]);
                    }
        }
        __syncthreads();
    }

    // ---- epilogue ----
    #pragma unroll
    for (int i = 0; i < 2; i++) {
        int row0 = m0 + wm * 32 + i * 16 + (lane >> 2);
        #pragma unroll
        for (int j = 0; j < 4; j++) {
            int pp = j >> 1, sub = j & 1;
            int col = n0 + wn * 32 + pp * 16 + sub * 8 + (lane & 3) * 2;
            float2 b2 = *(const float2*)(bias + col);
            #pragma unroll
            for (int half = 0; half < 2; half++) {
                int r = row0 + half * 8;
                float o0 = acc[i][j][half * 2 + 0] + b2.x;
                float o1 = acc[i][j][half * 2 + 1] + b2.y;
                size_t off = (size_t)r * M + col;
                if (epi == 1 || epi == 3) {
                    if (epi == 1) { o0 = softplus_f(o0); o1 = softplus_f(o1); }
                    else          { o0 *= scale; o1 *= scale; }
                    uint32_t uh, ul;
                    split2(o0, o1, uh, ul);
                    *(uint32_t*)(Chi + off) = uh;
                    *(uint32_t*)(Clo + off) = ul;
                } else {
                    if (epi == 2) {
                        float2 r2 = *(const float2*)(res + off);
                        o0 += r2.x; o1 += r2.y;
                    }
                    float2 o = {o0, o1};
                    *(float2*)(C + off) = o;
                }
            }
        }
    }
}

// ---------------- fused flash attention (HMMA, split-bf16) ------------------
// grid (16 qtiles, 32 bh), 256 thr (8 warps x 16 q-rows).
// Q pre-scaled by 1/8. Scores fp32 + alibi + causal, online softmax,
// P split in registers, O fp32 accumulators, output bf16 hi/lo split.
#define FTSTR 72
#define FQ_H 0
#define FQ_L (128*FTSTR*2)              // 18432
#define FK_H (2*128*FTSTR*2)            // 36864
#define FK_L (FK_H + 64*FTSTR*2)        // +9216
#define FV_H (FK_L + 64*FTSTR*2)
#define FV_L (FV_H + 64*FTSTR*2)
#define F_SMEM (FV_L + 64*FTSTR*2)      // 73728

__global__ void __launch_bounds__(256) fattn_kernel(
    const __nv_bfloat16* __restrict__ Qh_, const __nv_bfloat16* __restrict__ Ql_,
    const __nv_bfloat16* __restrict__ KVh, const __nv_bfloat16* __restrict__ KVl,
    __nv_bfloat16* __restrict__ Ohi, __nv_bfloat16* __restrict__ Olo)
{
    extern __shared__ char smem[];
    uint32_t sb = smem_u32(smem);
    int tid = threadIdx.x, lane = tid & 31, w = tid >> 5;
    int qtile = gridDim.x - 1 - blockIdx.x;   // heavy tiles first
    int bh = blockIdx.y;
    int b = bh >> 4, h = bh & 15;
    int q0 = qtile * 128;

    // ---- load Q tile (128 x 64) hi/lo ----
    #pragma unroll
    for (int u = 0; u < 4; u++) {
        int idx = tid + u * 256;          // 0..1023
        int r = idx >> 3, c = (idx & 7) * 8;
        size_t g = ((size_t)b * SSEQ + q0 + r) * DD + h * HD + c;
        uint32_t so = (uint32_t)(r * FTSTR + c) * 2;
        *(uint4*)(smem + FQ_H + so) = *(const uint4*)(Qh_ + g);
        *(uint4*)(smem + FQ_L + so) = *(const uint4*)(Ql_ + g);
    }
    __syncthreads();

    // Q A-fragments for this warp's 16 rows, 4 k16 blocks, hi+lo
    uint32_t qh[4][4], ql[4][4];
    uint32_t a_off = (uint32_t)((w * 16 + (lane & 15)) * FTSTR + ((lane >> 4) << 3)) * 2;
    #pragma unroll
    for (int ks = 0; ks < 4; ks++) {
        LDMX4(qh[ks][0], qh[ks][1], qh[ks][2], qh[ks][3], sb + FQ_H + a_off + ks * 32);
        LDMX4(ql[ks][0], ql[ks][1], ql[ks][2], ql[ks][3], sb + FQ_L + a_off + ks * 32);
    }

    float m0 = -1e30f, m1 = -1e30f, l0 = 0.0f, l1 = 0.0f;
    float o[8][4];
    #pragma unroll
    for (int j = 0; j < 8; j++)
        #pragma unroll
        for (int c = 0; c < 4; c++) o[j][c] = 0.0f;

    float slope = exp2f(-0.5f * (float)(h + 1));
    int row0 = q0 + w * 16 + (lane >> 2);   // first row this thread owns
    int warp_rmax = q0 + w * 16 + 15;
    int nkt = (q0 + 127) / 64 + 1;

    const __nv_bfloat16* kb_h = KVh + (size_t)b * SSEQ * 2 * DD + h * HD;
    const __nv_bfloat16* kb_l = KVl + (size_t)b * SSEQ * 2 * DD + h * HD;

    for (int kt = 0; kt < nkt; kt++) {
        // ---- cooperative load K,V tiles (64 x 64) hi/lo ----
        #pragma unroll
        for (int u = 0; u < 2; u++) {
            int idx = tid + u * 256;      // 0..511
            int r = idx >> 3, c = (idx & 7) * 8;
            size_t gk = (size_t)(kt * 64 + r) * (2 * DD) + c;
            uint32_t so = (uint32_t)(r * FTSTR + c) * 2;
            *(uint4*)(smem + FK_H + so) = *(const uint4*)(kb_h + gk);
            *(uint4*)(smem + FK_L + so) = *(const uint4*)(kb_l + gk);
            *(uint4*)(smem + FV_H + so) = *(const uint4*)(kb_h + gk + DD);
            *(uint4*)(smem + FV_L + so) = *(const uint4*)(kb_l + gk + DD);
        }
        __syncthreads();

        if (kt * 64 <= warp_rmax) {
            // ---- S = Q.K^T ----
            float S[8][4];
            #pragma unroll
            for (int j = 0; j < 8; j++)
                #pragma unroll
                for (int c = 0; c < 4; c++) S[j][c] = 0.0f;

            #pragma unroll
            for (int ks = 0; ks < 4; ks++) {
                #pragma unroll
                for (int p = 0; p < 4; p++) {
                    uint32_t kh[4], kl[4];
                    uint32_t boff = (uint32_t)((p * 16 + ((lane >> 4) << 3) + (lane & 7)) * FTSTR
                                               + (((lane >> 3) & 1) << 3)) * 2 + ks * 32;
                    LDMX4(kh[0], kh[1], kh[2], kh[3], sb + FK_H + boff);
                    LDMX4(kl[0], kl[1], kl[2], kl[3], sb + FK_L + boff);
                    MMA16816(S[p*2+0], qh[ks], kh[0], kh[1]);
                    MMA16816(S[p*2+1], qh[ks], kh[2], kh[3]);
                    MMA16816(S[p*2+0], qh[ks], kl[0], kl[1]);
                    MMA16816(S[p*2+1], qh[ks], kl[2], kl[3]);
                    MMA16816(S[p*2+0], ql[ks], kh[0], kh[1]);
                    MMA16816(S[p*2+1], ql[ks], kh[2], kh[3]);
                }
            }

            // ---- alibi + causal mask ----
            #pragma unroll
            for (int j = 0; j < 8; j++) {
                int col = kt * 64 + j * 8 + (lane & 3) * 2;
                S[j][0] = (col     <= row0)     ? S[j][0] + slope * (float)(col     - row0)     : -1e30f;
                S[j][1] = (col + 1 <= row0)     ? S[j][1] + slope * (float)(col + 1 - row0)     : -1e30f;
                S[j][2] = (col     <= row0 + 8) ? S[j][2] + slope * (float)(col     - row0 - 8) : -1e30f;
                S[j][3] = (col + 1 <= row0 + 8) ? S[j][3] + slope * (float)(col + 1 - row0 - 8) : -1e30f;
            }

            // ---- online softmax update ----
            float rm0 = -1e30f, rm1 = -1e30f;
            #pragma unroll
            for (int j = 0; j < 8; j++) {
                rm0 = fmaxf(rm0, fmaxf(S[j][0], S[j][1]));
                rm1 = fmaxf(rm1, fmaxf(S[j][2], S[j][3]));
            }
            rm0 = fmaxf(rm0, __shfl_xor_sync(0xffffffffu, rm0, 1));
            rm0 = fmaxf(rm0, __shfl_xor_sync(0xffffffffu, rm0, 2));
            rm1 = fmaxf(rm1, __shfl_xor_sync(0xffffffffu, rm1, 1));
            rm1 = fmaxf(rm1, __shfl_xor_sync(0xffffffffu, rm1, 2));
            float mn0 = fmaxf(m0, rm0), mn1 = fmaxf(m1, rm1);
            float al0 = expf(m0 - mn0),  al1 = expf(m1 - mn1);
            m0 = mn0; m1 = mn1;

            float ps0 = 0.0f, ps1 = 0.0f;
            #pragma unroll
            for (int j = 0; j < 8; j++) {
                S[j][0] = expf(S[j][0] - m0);
                S[j][1] = expf(S[j][1] - m0);
                S[j][2] = expf(S[j][2] - m1);
                S[j][3] = expf(S[j][3] - m1);
                ps0 += S[j][0] + S[j][1];
                ps1 += S[j][2] + S[j][3];
            }
            l0 = l0 * al0 + ps0;
            l1 = l1 * al1 + ps1;
            #pragma unroll
            for (int j = 0; j < 8; j++) {
                o[j][0] *= al0; o[j][1] *= al0;
                o[j][2] *= al1; o[j][3] *= al1;
            }

            // ---- O += P.V (P split in registers) ----
            #pragma unroll
            for (int j = 0; j < 4; j++) {
                uint32_t ph[4], pl[4];
                split2(S[2*j  ][0], S[2*j  ][1], ph[0], pl[0]);
                split2(S[2*j  ][2], S[2*j  ][3], ph[1], pl[1]);
                split2(S[2*j+1][0], S[2*j+1][1], ph[2], pl[2]);
                split2(S[2*j+1][2], S[2*j+1][3], ph[3], pl[3]);
                #pragma unroll
                for (int pp = 0; pp < 4; pp++) {
                    uint32_t vh[4], vl[4];
                    uint32_t voff = (uint32_t)((j * 16 + (lane & 15)) * FTSTR
                                               + pp * 16 + ((lane >> 4) << 3)) * 2;
                    LDMX4T(vh[0], vh[1], vh[2], vh[3], sb + FV_H + voff);
                    LDMX4T(vl[0], vl[1], vl[2], vl[3], sb + FV_L + voff);
                    MMA16816(o[pp*2+0], ph, vh[0], vh[1]);
                    MMA16816(o[pp*2+1], ph, vh[2], vh[3]);
                    MMA16816(o[pp*2+0], ph, vl[0], vl[1]);
                    MMA16816(o[pp*2+1], ph, vl[2], vl[3]);
                    MMA16816(o[pp*2+0], pl, vh[0], vh[1]);
                    MMA16816(o[pp*2+1], pl, vh[2], vh[3]);
                }
            }
        }
        __syncthreads();
    }

    // ---- finalize: reduce l across quad, normalize, split-write ----
    l0 += __shfl_xor_sync(0xffffffffu, l0, 1);
    l0 += __shfl_xor_sync(0xffffffffu, l0, 2);
    l1 += __shfl_xor_sync(0xffffffffu, l1, 1);
    l1 += __shfl_xor_sync(0xffffffffu, l1, 2);
    float i0 = 1.0f / l0, i1 = 1.0f / l1;

    size_t gr0 = (size_t)b * SSEQ + q0 + w * 16 + (lane >> 2);
    #pragma unroll
    for (int j = 0; j < 8; j++) {
        int col = h * HD + j * 8 + (lane & 3) * 2;
        uint32_t uh, ul;
        split2(o[j][0] * i0, o[j][1] * i0, uh, ul);
        *(uint32_t*)(Ohi + gr0 * DD + col) = uh;
        *(uint32_t*)(Olo + gr0 * DD + col) = ul;
        split2(o[j][2] * i1, o[j][3] * i1, uh, ul);
        *(uint32_t*)(Ohi + (gr0 + 8) * DD + col) = uh;
        *(uint32_t*)(Olo + (gr0 + 8) * DD + col) = ul;
    }
}

// ---------------- host orchestration ---------------------------------------
extern "C" void kernel_launch(void* const* d_in, const int* in_sizes, int n_in,
                              void* d_out, int out_size)
{
    const float *ts, *fg, *fb, *wq, *bq, *wkv, *bkv, *wo, *bo,
                *w1, *b1, *w2, *b2, *ag, *ab, *ffg, *ffb;
    if (in_sizes[1] == 1024) {
        ts  = (const float*)d_in[0];
        fg  = (const float*)d_in[1];  fb  = (const float*)d_in[2];
        wq  = (const float*)d_in[3];  bq  = (const float*)d_in[4];
        wkv = (const float*)d_in[5];  bkv = (const float*)d_in[6];
        wo  = (const float*)d_in[7];  bo  = (const float*)d_in[8];
        w1  = (const float*)d_in[9];  b1  = (const float*)d_in[10];
        w2  = (const float*)d_in[11]; b2  = (const float*)d_in[12];
        ag  = (const float*)d_in[13]; ab  = (const float*)d_in[14];
        ffg = (const float*)d_in[15]; ffb = (const float*)d_in[16];
    } else {
        ts  = (const float*)d_in[0];
        wq  = (const float*)d_in[1];  bq  = (const float*)d_in[2];
        wkv = (const float*)d_in[3];  bkv = (const float*)d_in[4];
        wo  = (const float*)d_in[5];  bo  = (const float*)d_in[6];
        w1  = (const float*)d_in[7];  b1  = (const float*)d_in[8];
        w2  = (const float*)d_in[9];  b2  = (const float*)d_in[10];
        ag  = (const float*)d_in[11]; ab  = (const float*)d_in[12];
        ffg = (const float*)d_in[13]; ffb = (const float*)d_in[14];
        fg  = (const float*)d_in[15]; fb  = (const float*)d_in[16];
    }

    float *x;
    __nv_bfloat16 *hh, *hl, *qh_, *ql_, *kvh, *kvl, *ath, *atl, *fh, *fl;
    __nv_bfloat16 *wqh, *wql, *wkvh, *wkvl, *woh, *wol, *w1h, *w1l, *w2h, *w2l;
    cudaGetSymbolAddress((void**)&x,    g_x);
    cudaGetSymbolAddress((void**)&hh,   g_h_hi);
    cudaGetSymbolAddress((void**)&hl,   g_h_lo);
    cudaGetSymbolAddress((void**)&qh_,  g_q_hi);
    cudaGetSymbolAddress((void**)&ql_,  g_q_lo);
    cudaGetSymbolAddress((void**)&kvh,  g_kv_hi);
    cudaGetSymbolAddress((void**)&kvl,  g_kv_lo);
    cudaGetSymbolAddress((void**)&ath,  g_att_hi);
    cudaGetSymbolAddress((void**)&atl,  g_att_lo);
    cudaGetSymbolAddress((void**)&fh,   g_f_hi);
    cudaGetSymbolAddress((void**)&fl,   g_f_lo);
    cudaGetSymbolAddress((void**)&wqh,  g_wq_h);
    cudaGetSymbolAddress((void**)&wql,  g_wq_l);
    cudaGetSymbolAddress((void**)&wkvh, g_wkv_h);
    cudaGetSymbolAddress((void**)&wkvl, g_wkv_l);
    cudaGetSymbolAddress((void**)&woh,  g_wo_h);
    cudaGetSymbolAddress((void**)&wol,  g_wo_l);
    cudaGetSymbolAddress((void**)&w1h,  g_w1_h);
    cudaGetSymbolAddress((void**)&w1l,  g_w1_l);
    cudaGetSymbolAddress((void**)&w2h,  g_w2_h);
    cudaGetSymbolAddress((void**)&w2l,  g_w2_l);

    cudaFuncSetAttribute(tgemm_kernel,
                         cudaFuncAttributeMaxDynamicSharedMemorySize, TG_SMEM);
    cudaFuncSetAttribute(fattn_kernel,
                         cudaFuncAttributeMaxDynamicSharedMemorySize, F_SMEM);

    cudaMemcpyAsync(x, ts, sizeof(float) * (size_t)NT * DD,
                    cudaMemcpyDeviceToDevice, 0);

    // weight transpose + split (per layer)
    for (int l = 0; l < NL; l++) {
        dim3 blk(32, 8);
        wconv_kernel<<<dim3(DD/32, DD/32), blk>>>(
            wq + (size_t)l*DD*DD, wqh + (size_t)l*DD*DD, wql + (size_t)l*DD*DD, DD, DD);
        wconv_kernel<<<dim3(2*DD/32, DD/32), blk>>>(
            wkv + (size_t)l*DD*2*DD, wkvh + (size_t)l*DD*2*DD, wkvl + (size_t)l*DD*2*DD, DD, 2*DD);
        wconv_kernel<<<dim3(DD/32, DD/32), blk>>>(
            wo + (size_t)l*DD*DD, woh + (size_t)l*DD*DD, wol + (size_t)l*DD*DD, DD, DD);
        wconv_kernel<<<dim3(FF/32, DD/32), blk>>>(
            w1 + (size_t)l*DD*FF, w1h + (size_t)l*DD*FF, w1l + (size_t)l*DD*FF, DD, FF);
        wconv_kernel<<<dim3(DD/32, FF/32), blk>>>(
            w2 + (size_t)l*FF*DD, w2h + (size_t)l*FF*DD, w2l + (size_t)l*FF*DD, FF, DD);
    }

    for (int l = 0; l < NL; l++) {
        // pre-attention LN -> bf16 split
        ln_bf16_kernel<<<NT, 256>>>(x, ag + (size_t)l*DD, ab + (size_t)l*DD, hh, hl);
        // Q = (h@wq + bq)/8 -> bf16 split
        tgemm_kernel<<<dim3(DD/64, NT/128), 256, TG_SMEM>>>(
            hh, hl, wqh + (size_t)l*DD*DD, wql + (size_t)l*DD*DD,
            bq + (size_t)l*DD, nullptr, nullptr, qh_, ql_, DD, DD, 3, 0.125f);
        // KV = h@wkv + bkv -> bf16 split
        tgemm_kernel<<<dim3(2*DD/64, NT/128), 256, TG_SMEM>>>(
            hh, hl, wkvh + (size_t)l*DD*2*DD, wkvl + (size_t)l*DD*2*DD,
            bkv + (size_t)l*2*DD, nullptr, nullptr, kvh, kvl, DD, 2*DD, 3, 1.0f);
        // fused flash attention -> att hi/lo
        fattn_kernel<<<dim3(SSEQ/128, BB*HH), 256, F_SMEM>>>(
            qh_, ql_, kvh, kvl, ath, atl);
        // x = heads@wo + bo + x
        tgemm_kernel<<<dim3(DD/64, NT/128), 256, TG_SMEM>>>(
            ath, atl, woh + (size_t)l*DD*DD, wol + (size_t)l*DD*DD,
            bo + (size_t)l*DD, x, x, nullptr, nullptr, DD, DD, 2, 1.0f);
        // pre-FFN LN -> bf16 split
        ln_bf16_kernel<<<NT, 256>>>(x, ffg + (size_t)l*DD, ffb + (size_t)l*DD, hh, hl);
        // f = softplus(h@w1 + b1) -> bf16 split
        tgemm_kernel<<<dim3(FF/64, NT/128), 256, TG_SMEM>>>(
            hh, hl, w1h + (size_t)l*DD*FF, w1l + (size_t)l*DD*FF,
            b1 + (size_t)l*FF, nullptr, nullptr, fh, fl, DD, FF, 1, 1.0f);
        // x = f@w2 + b2 + x
        tgemm_kernel<<<dim3(DD/64, NT/128), 256, TG_SMEM>>>(
            fh, fl, w2h + (size_t)l*FF*DD, w2l + (size_t)l*FF*DD,
            b2 + (size_t)l*DD, x, x, nullptr, nullptr, FF, DD, 2, 1.0f);
    }

    // final layernorm -> output (fp32)
    ln_kernel<<<NT, 256>>>(x, fg, fb, (float*)d_out);
}

// round 9
// speedup vs baseline: 2.5580x; 1.0688x over previous
#include <cuda_runtime.h>
#include <cuda_bf16.h>
#include <math.h>
#include <stdint.h>

// Problem constants
#define BB 2
#define SSEQ 2048
#define DD 1024
#define HH 16
#define HD 64
#define FF 4096
#define NL 8
#define NT (BB*SSEQ)   // 4096 token rows

// ---------------- scratch (device globals: allocation-guard safe) ----------
__device__ float g_x  [NT*DD];            // residual stream fp32

__device__ __nv_bfloat16 g_h_hi [NT*DD];  // LN out split
__device__ __nv_bfloat16 g_h_lo [NT*DD];
__device__ __nv_bfloat16 g_q_hi [NT*DD];  // Q split (pre-scaled by 1/8)
__device__ __nv_bfloat16 g_q_lo [NT*DD];
__device__ __nv_bfloat16 g_kv_hi[NT*2*DD];// K|V split
__device__ __nv_bfloat16 g_kv_lo[NT*2*DD];
__device__ __nv_bfloat16 g_att_hi[NT*DD]; // attention heads split
__device__ __nv_bfloat16 g_att_lo[NT*DD];
__device__ __nv_bfloat16 g_f_hi [NT*FF];  // FFN hidden split
__device__ __nv_bfloat16 g_f_lo [NT*FF];

// transposed+split weights, [out][in] K-major bf16
__device__ __nv_bfloat16 g_wq_h [NL*DD*DD];
__device__ __nv_bfloat16 g_wq_l [NL*DD*DD];
__device__ __nv_bfloat16 g_wkv_h[NL*DD*2*DD];
__device__ __nv_bfloat16 g_wkv_l[NL*DD*2*DD];
__device__ __nv_bfloat16 g_wo_h [NL*DD*DD];
__device__ __nv_bfloat16 g_wo_l [NL*DD*DD];
__device__ __nv_bfloat16 g_w1_h [NL*DD*FF];
__device__ __nv_bfloat16 g_w1_l [NL*DD*FF];
__device__ __nv_bfloat16 g_w2_h [NL*FF*DD];
__device__ __nv_bfloat16 g_w2_l [NL*FF*DD];

// ---------------- small helpers --------------------------------------------
__device__ __forceinline__ float softplus_f(float x) {
    return fmaxf(x, 0.0f) + log1pf(expf(-fabsf(x)));
}
__device__ __forceinline__ uint32_t smem_u32(const void* p) {
    uint32_t a;
    asm("{ .reg .u64 t; cvta.to.shared.u64 t, %1; cvt.u32.u64 %0, t; }"
        : "=r"(a) : "l"(p));
    return a;
}
__device__ __forceinline__ void cp16(uint32_t s, const void* g) {
    asm volatile("cp.async.cg.shared.global [%0], [%1], 16;" :: "r"(s), "l"(g));
}
#define CP_COMMIT() asm volatile("cp.async.commit_group;")
#define CP_WAIT0()  asm volatile("cp.async.wait_group 0;")
#define CP_WAIT1()  asm volatile("cp.async.wait_group 1;")

// split fp32 into hi/lo bf16 pair packed as bf16x2 words
__device__ __forceinline__ void split2(float a, float b, uint32_t& hi, uint32_t& lo) {
    __nv_bfloat162 h = __floats2bfloat162_rn(a, b);
    float ra = a - __bfloat162float(h.x);
    float rb = b - __bfloat162float(h.y);
    __nv_bfloat162 l = __floats2bfloat162_rn(ra, rb);
    hi = *(uint32_t*)&h;
    lo = *(uint32_t*)&l;
}

#define LDMX4(R0,R1,R2,R3,ADDR) \
    asm volatile("ldmatrix.sync.aligned.m8n8.x4.shared.b16 {%0,%1,%2,%3}, [%4];" \
        : "=r"(R0),"=r"(R1),"=r"(R2),"=r"(R3) : "r"(ADDR))

#define LDMX4T(R0,R1,R2,R3,ADDR) \
    asm volatile("ldmatrix.sync.aligned.m8n8.x4.trans.shared.b16 {%0,%1,%2,%3}, [%4];" \
        : "=r"(R0),"=r"(R1),"=r"(R2),"=r"(R3) : "r"(ADDR))

#define MMA16816(C, A, B0, B1) \
    asm volatile("mma.sync.aligned.m16n8k16.row.col.f32.bf16.bf16.f32 " \
        "{%0,%1,%2,%3}, {%4,%5,%6,%7}, {%8,%9}, {%0,%1,%2,%3};" \
        : "+f"((C)[0]),"+f"((C)[1]),"+f"((C)[2]),"+f"((C)[3]) \
        : "r"((A)[0]),"r"((A)[1]),"r"((A)[2]),"r"((A)[3]), "r"(B0),"r"(B1))

// ---------------- weight transpose + split (all layers in grid.z) -----------
__global__ void wconv_kernel(const float* __restrict__ W,
                             __nv_bfloat16* __restrict__ oh,
                             __nv_bfloat16* __restrict__ ol,
                             int K, int M)
{
    size_t loff = (size_t)blockIdx.z * K * M;
    W  += loff; oh += loff; ol += loff;
    __shared__ float t[32][33];
    int m0 = blockIdx.x * 32, k0 = blockIdx.y * 32;
    int tx = threadIdx.x, ty = threadIdx.y;  // 32 x 8
    #pragma unroll
    for (int j = 0; j < 4; j++)
        t[ty + 8 * j][tx] = W[(size_t)(k0 + ty + 8 * j) * M + m0 + tx];
    __syncthreads();
    #pragma unroll
    for (int j = 0; j < 4; j++) {
        float v = t[tx][ty + 8 * j];
        int m = m0 + ty + 8 * j, k = k0 + tx;
        __nv_bfloat16 h = __float2bfloat16(v);
        oh[(size_t)m * K + k] = h;
        ol[(size_t)m * K + k] = __float2bfloat16(v - __bfloat162float(h));
    }
}

// ---------------- LayerNorm (fp32 out) --------------------------------------
__global__ void ln_kernel(const float* __restrict__ in,
                          const float* __restrict__ gamma,
                          const float* __restrict__ beta,
                          float* __restrict__ out)
{
    int row = blockIdx.x;
    int tid = threadIdx.x;
    const float* p = in + (size_t)row * DD;
    float4 v = *(const float4*)(p + tid * 4);
    float s  = v.x + v.y + v.z + v.w;
    float sq = v.x*v.x + v.y*v.y + v.z*v.z + v.w*v.w;
    __shared__ float sm1[8], sm2[8];
    #pragma unroll
    for (int o = 16; o > 0; o >>= 1) {
        s  += __shfl_xor_sync(0xffffffffu, s,  o);
        sq += __shfl_xor_sync(0xffffffffu, sq, o);
    }
    if ((tid & 31) == 0) { sm1[tid >> 5] = s; sm2[tid >> 5] = sq; }
    __syncthreads();
    if (tid < 32) {
        s  = (tid < 8) ? sm1[tid] : 0.0f;
        sq = (tid < 8) ? sm2[tid] : 0.0f;
        #pragma unroll
        for (int o = 4; o > 0; o >>= 1) {
            s  += __shfl_xor_sync(0xffffffffu, s,  o);
            sq += __shfl_xor_sync(0xffffffffu, sq, o);
        }
        if (tid == 0) { sm1[0] = s; sm2[0] = sq; }
    }
    __syncthreads();
    float mean = sm1[0] * (1.0f / DD);
    float var  = sm2[0] * (1.0f / DD) - mean * mean;
    float rs   = rsqrtf(var + 1e-3f);
    float4 g  = *(const float4*)(gamma + tid * 4);
    float4 be = *(const float4*)(beta  + tid * 4);
    float4 o4;
    o4.x = (v.x - mean) * rs * g.x + be.x;
    o4.y = (v.y - mean) * rs * g.y + be.y;
    o4.z = (v.z - mean) * rs * g.z + be.z;
    o4.w = (v.w - mean) * rs * g.w + be.w;
    *(float4*)(out + (size_t)row * DD + tid * 4) = o4;
}

// ---------------- LayerNorm (bf16 hi/lo out) --------------------------------
__global__ void ln_bf16_kernel(const float* __restrict__ in,
                               const float* __restrict__ gamma,
                               const float* __restrict__ beta,
                               __nv_bfloat16* __restrict__ ohi,
                               __nv_bfloat16* __restrict__ olo)
{
    int row = blockIdx.x;
    int tid = threadIdx.x;
    const float* p = in + (size_t)row * DD;
    float4 v = *(const float4*)(p + tid * 4);
    float s  = v.x + v.y + v.z + v.w;
    float sq = v.x*v.x + v.y*v.y + v.z*v.z + v.w*v.w;
    __shared__ float sm1[8], sm2[8];
    #pragma unroll
    for (int o = 16; o > 0; o >>= 1) {
        s  += __shfl_xor_sync(0xffffffffu, s,  o);
        sq += __shfl_xor_sync(0xffffffffu, sq, o);
    }
    if ((tid & 31) == 0) { sm1[tid >> 5] = s; sm2[tid >> 5] = sq; }
    __syncthreads();
    if (tid < 32) {
        s  = (tid < 8) ? sm1[tid] : 0.0f;
        sq = (tid < 8) ? sm2[tid] : 0.0f;
        #pragma unroll
        for (int o = 4; o > 0; o >>= 1) {
            s  += __shfl_xor_sync(0xffffffffu, s,  o);
            sq += __shfl_xor_sync(0xffffffffu, sq, o);
        }
        if (tid == 0) { sm1[0] = s; sm2[0] = sq; }
    }
    __syncthreads();
    float mean = sm1[0] * (1.0f / DD);
    float var  = sm2[0] * (1.0f / DD) - mean * mean;
    float rs   = rsqrtf(var + 1e-3f);
    float4 g  = *(const float4*)(gamma + tid * 4);
    float4 be = *(const float4*)(beta  + tid * 4);
    float a = (v.x - mean) * rs * g.x + be.x;
    float b = (v.y - mean) * rs * g.y + be.y;
    float c = (v.z - mean) * rs * g.z + be.z;
    float d = (v.w - mean) * rs * g.w + be.w;
    uint2 uh, ul;
    split2(a, b, uh.x, ul.x);
    split2(c, d, uh.y, ul.y);
    size_t off = (size_t)row * DD + tid * 4;
    *(uint2*)(ohi + off) = uh;
    *(uint2*)(olo + off) = ul;
}

// ---------------- HMMA split-bf16 GEMM, cp.async 2-stage pipeline -----------
// C[NT, M] = A[NT, K] @ B[M, K]^T (+bias), K chunks of 64.
// Block: 128 rows x 64 cols, 8 warps (4m x 2n), warp tile 32x32.
// epi: 0 = bias -> fp32 ; 1 = bias+softplus -> bf16 hi/lo ;
//      2 = bias+res -> fp32 ; 3 = (bias)*scale -> bf16 hi/lo
#define TSTR 72                      // smem row stride in bf16 elems (144 B)
#define SA_H 0
#define SA_L 18432                   // 128*72*2
#define SB_H 36864
#define SB_L 46080
#define TG_STAGE 55296
#define TG_SMEM (2*TG_STAGE)         // 110592

#define TG_LOADS(kb, stg) do {                                            \
    uint32_t base_ = sb + (uint32_t)(stg) * TG_STAGE;                     \
    _Pragma("unroll")                                                     \
    for (int u = 0; u < 4; u++) {                                         \
        int idx = tid + u * 256;                                          \
        int r = idx >> 3, c = (idx & 7) * 8;                              \
        size_t g = (size_t)(m0 + r) * K + (kb) + c;                       \
        uint32_t so = (uint32_t)(r * TSTR + c) * 2;                       \
        cp16(base_ + SA_H + so, Ah + g);                                  \
        cp16(base_ + SA_L + so, Al + g);                                  \
    }                                                                     \
    _Pragma("unroll")                                                     \
    for (int u = 0; u < 2; u++) {                                         \
        int idx = tid + u * 256;                                          \
        int r = idx >> 3, c = (idx & 7) * 8;                              \
        size_t g = (size_t)(n0 + r) * K + (kb) + c;                       \
        uint32_t so = (uint32_t)(r * TSTR + c) * 2;                       \
        cp16(base_ + SB_H + so, Bh + g);                                  \
        cp16(base_ + SB_L + so, Bl + g);                                  \
    }                                                                     \
} while (0)

__global__ void __launch_bounds__(256) tgemm_kernel(
    const __nv_bfloat16* __restrict__ Ah, const __nv_bfloat16* __restrict__ Al,
    const __nv_bfloat16* __restrict__ Bh, const __nv_bfloat16* __restrict__ Bl,
    const float* __restrict__ bias, const float* __restrict__ res,
    float* __restrict__ C, __nv_bfloat16* __restrict__ Chi,
    __nv_bfloat16* __restrict__ Clo, int K, int M, int epi, float scale)
{
    extern __shared__ char smem[];
    uint32_t sb = smem_u32(smem);
    int tid  = threadIdx.x;
    int lane = tid & 31;
    int w    = tid >> 5;
    int wm   = w & 3;
    int wn   = w >> 2;

    int m0 = blockIdx.y * 128;
    int n0 = blockIdx.x * 64;

    float acc[2][4][4];
    #pragma unroll
    for (int i = 0; i < 2; i++)
        #pragma unroll
        for (int j = 0; j < 4; j++)
            #pragma unroll
            for (int c = 0; c < 4; c++) acc[i][j][c] = 0.0f;

    uint32_t a_off = (uint32_t)((wm * 32 + (lane & 15)) * TSTR + ((lane >> 4) << 3)) * 2;
    uint32_t b_off = (uint32_t)((wn * 32 + ((lane >> 4) << 3) + (lane & 7)) * TSTR
                                + (((lane >> 3) & 1) << 3)) * 2;

    int nch = K >> 6;
    TG_LOADS(0, 0);
    CP_COMMIT();

    for (int kc = 0; kc < nch; kc++) {
        if (kc + 1 < nch) {
            TG_LOADS((kc + 1) * 64, (kc + 1) & 1);
            CP_COMMIT();
            CP_WAIT1();
        } else {
            CP_WAIT0();
        }
        __syncthreads();

        uint32_t stb = sb + (uint32_t)(kc & 1) * TG_STAGE;
        #pragma unroll
        for (int ks = 0; ks < 4; ks++) {
            uint32_t kb = (uint32_t)(ks * 16) * 2;
            uint32_t ah[2][4], al[2][4], bh[2][4], bl[2][4];
            #pragma unroll
            for (int i = 0; i < 2; i++) {
                uint32_t aa = stb + SA_H + a_off + (uint32_t)(i * 16 * TSTR) * 2 + kb;
                LDMX4(ah[i][0], ah[i][1], ah[i][2], ah[i][3], aa);
                uint32_t aa2 = stb + SA_L + a_off + (uint32_t)(i * 16 * TSTR) * 2 + kb;
                LDMX4(al[i][0], al[i][1], al[i][2], al[i][3], aa2);
            }
            #pragma unroll
            for (int p = 0; p < 2; p++) {
                uint32_t ba = stb + SB_H + b_off + (uint32_t)(p * 16 * TSTR) * 2 + kb;
                LDMX4(bh[p][0], bh[p][1], bh[p][2], bh[p][3], ba);
                uint32_t ba2 = stb + SB_L + b_off + (uint32_t)(p * 16 * TSTR) * 2 + kb;
                LDMX4(bl[p][0], bl[p][1], bl[p][2], bl[p][3], ba2);
            }
            #pragma unroll
            for (int i = 0; i < 2; i++)
                #pragma unroll
                for (int p = 0; p < 2; p++)
                    #pragma unroll
                    for (int sub = 0; sub < 2; sub++) {
                        int j = p * 2 + sub;
                        MMA16816(acc[i][j], ah[i], bh[p][sub * 2], bh[p][sub * 2 + 1]);
                        MMA16816(acc[i][j], ah[i], bl[p][sub * 2], bl[p][sub * 2 + 1]);
                        MMA16816(acc[i][j], al[i], bh[p][sub * 2], bh[p][sub * 2 + 1]);
                    }
        }
        __syncthreads();
    }

    // ---- epilogue ----
    #pragma unroll
    for (int i = 0; i < 2; i++) {
        int row0 = m0 + wm * 32 + i * 16 + (lane >> 2);
        #pragma unroll
        for (int j = 0; j < 4; j++) {
            int pp = j >> 1, sub = j & 1;
            int col = n0 + wn * 32 + pp * 16 + sub * 8 + (lane & 3) * 2;
            float2 b2 = *(const float2*)(bias + col);
            #pragma unroll
            for (int half = 0; half < 2; half++) {
                int r = row0 + half * 8;
                float o0 = acc[i][j][half * 2 + 0] + b2.x;
                float o1 = acc[i][j][half * 2 + 1] + b2.y;
                size_t off = (size_t)r * M + col;
                if (epi == 1 || epi == 3) {
                    if (epi == 1) { o0 = softplus_f(o0); o1 = softplus_f(o1); }
                    else          { o0 *= scale; o1 *= scale; }
                    uint32_t uh, ul;
                    split2(o0, o1, uh, ul);
                    *(uint32_t*)(Chi + off) = uh;
                    *(uint32_t*)(Clo + off) = ul;
                } else {
                    if (epi == 2) {
                        float2 r2 = *(const float2*)(res + off);
                        o0 += r2.x; o1 += r2.y;
                    }
                    float2 o = {o0, o1};
                    *(float2*)(C + off) = o;
                }
            }
        }
    }
}

// ---------------- fused flash attention, cp.async K/V double buffer ---------
// grid (16 qtiles, 32 bh), 256 thr (8 warps x 16 q-rows).
#define FTSTR 72
#define FQ_H 0
#define FQ_L 18432
#define FKV0 36864                      // stage base; stage size 36864
#define FKV_STAGE 36864
#define FK_H 0
#define FK_L 9216
#define FV_H 18432
#define FV_L 27648
#define F_SMEM (FKV0 + 2*FKV_STAGE)     // 110592

#define F_LOADKV(kt, stg) do {                                            \
    uint32_t base_ = sb + FKV0 + (uint32_t)(stg) * FKV_STAGE;             \
    _Pragma("unroll")                                                     \
    for (int u = 0; u < 2; u++) {                                         \
        int idx = tid + u * 256;                                          \
        int r = idx >> 3, c = (idx & 7) * 8;                              \
        size_t gk = (size_t)((kt) * 64 + r) * (2 * DD) + c;               \
        uint32_t so = (uint32_t)(r * FTSTR + c) * 2;                      \
        cp16(base_ + FK_H + so, kb_h + gk);                               \
        cp16(base_ + FK_L + so, kb_l + gk);                               \
        cp16(base_ + FV_H + so, kb_h + gk + DD);                          \
        cp16(base_ + FV_L + so, kb_l + gk + DD);                          \
    }                                                                     \
} while (0)

__global__ void __launch_bounds__(256) fattn_kernel(
    const __nv_bfloat16* __restrict__ Qh_, const __nv_bfloat16* __restrict__ Ql_,
    const __nv_bfloat16* __restrict__ KVh, const __nv_bfloat16* __restrict__ KVl,
    __nv_bfloat16* __restrict__ Ohi, __nv_bfloat16* __restrict__ Olo)
{
    extern __shared__ char smem[];
    uint32_t sb = smem_u32(smem);
    int tid = threadIdx.x, lane = tid & 31, w = tid >> 5;
    int qtile = gridDim.x - 1 - blockIdx.x;   // heavy tiles first
    int bh = blockIdx.y;
    int b = bh >> 4, h = bh & 15;
    int q0 = qtile * 128;

    const __nv_bfloat16* kb_h = KVh + (size_t)b * SSEQ * 2 * DD + h * HD;
    const __nv_bfloat16* kb_l = KVl + (size_t)b * SSEQ * 2 * DD + h * HD;

    // prefetch K/V tile 0 while loading Q
    F_LOADKV(0, 0);
    CP_COMMIT();

    // ---- load Q tile (128 x 64) hi/lo ----
    #pragma unroll
    for (int u = 0; u < 4; u++) {
        int idx = tid + u * 256;
        int r = idx >> 3, c = (idx & 7) * 8;
        size_t g = ((size_t)b * SSEQ + q0 + r) * DD + h * HD + c;
        uint32_t so = (uint32_t)(r * FTSTR + c) * 2;
        *(uint4*)(smem + FQ_H + so) = *(const uint4*)(Qh_ + g);
        *(uint4*)(smem + FQ_L + so) = *(const uint4*)(Ql_ + g);
    }
    __syncthreads();

    uint32_t qh[4][4], ql[4][4];
    uint32_t a_off = (uint32_t)((w * 16 + (lane & 15)) * FTSTR + ((lane >> 4) << 3)) * 2;
    #pragma unroll
    for (int ks = 0; ks < 4; ks++) {
        LDMX4(qh[ks][0], qh[ks][1], qh[ks][2], qh[ks][3], sb + FQ_H + a_off + ks * 32);
        LDMX4(ql[ks][0], ql[ks][1], ql[ks][2], ql[ks][3], sb + FQ_L + a_off + ks * 32);
    }

    float m0 = -1e30f, m1 = -1e30f, l0 = 0.0f, l1 = 0.0f;
    float o[8][4];
    #pragma unroll
    for (int j = 0; j < 8; j++)
        #pragma unroll
        for (int c = 0; c < 4; c++) o[j][c] = 0.0f;

    float slope = exp2f(-0.5f * (float)(h + 1));
    int row0 = q0 + w * 16 + (lane >> 2);
    int warp_rmax = q0 + w * 16 + 15;
    int nkt = (q0 + 127) / 64 + 1;

    for (int kt = 0; kt < nkt; kt++) {
        if (kt + 1 < nkt) {
            F_LOADKV(kt + 1, (kt + 1) & 1);
            CP_COMMIT();
            CP_WAIT1();
        } else {
            CP_WAIT0();
        }
        __syncthreads();

        uint32_t stb = sb + FKV0 + (uint32_t)(kt & 1) * FKV_STAGE;

        if (kt * 64 <= warp_rmax) {
            // ---- S = Q.K^T ----
            float S[8][4];
            #pragma unroll
            for (int j = 0; j < 8; j++)
                #pragma unroll
                for (int c = 0; c < 4; c++) S[j][c] = 0.0f;

            #pragma unroll
            for (int ks = 0; ks < 4; ks++) {
                #pragma unroll
                for (int p = 0; p < 4; p++) {
                    uint32_t kh[4], kl[4];
                    uint32_t boff = (uint32_t)((p * 16 + ((lane >> 4) << 3) + (lane & 7)) * FTSTR
                                               + (((lane >> 3) & 1) << 3)) * 2 + ks * 32;
                    LDMX4(kh[0], kh[1], kh[2], kh[3], stb + FK_H + boff);
                    LDMX4(kl[0], kl[1], kl[2], kl[3], stb + FK_L + boff);
                    MMA16816(S[p*2+0], qh[ks], kh[0], kh[1]);
                    MMA16816(S[p*2+1], qh[ks], kh[2], kh[3]);
                    MMA16816(S[p*2+0], qh[ks], kl[0], kl[1]);
                    MMA16816(S[p*2+1], qh[ks], kl[2], kl[3]);
                    MMA16816(S[p*2+0], ql[ks], kh[0], kh[1]);
                    MMA16816(S[p*2+1], ql[ks], kh[2], kh[3]);
                }
            }

            // ---- alibi + causal mask ----
            #pragma unroll
            for (int j = 0; j < 8; j++) {
                int col = kt * 64 + j * 8 + (lane & 3) * 2;
                S[j][0] = (col     <= row0)     ? S[j][0] + slope * (float)(col     - row0)     : -1e30f;
                S[j][1] = (col + 1 <= row0)     ? S[j][1] + slope * (float)(col + 1 - row0)     : -1e30f;
                S[j][2] = (col     <= row0 + 8) ? S[j][2] + slope * (float)(col     - row0 - 8) : -1e30f;
                S[j][3] = (col + 1 <= row0 + 8) ? S[j][3] + slope * (float)(col + 1 - row0 - 8) : -1e30f;
            }

            // ---- online softmax update ----
            float rm0 = -1e30f, rm1 = -1e30f;
            #pragma unroll
            for (int j = 0; j < 8; j++) {
                rm0 = fmaxf(rm0, fmaxf(S[j][0], S[j][1]));
                rm1 = fmaxf(rm1, fmaxf(S[j][2], S[j][3]));
            }
            rm0 = fmaxf(rm0, __shfl_xor_sync(0xffffffffu, rm0, 1));
            rm0 = fmaxf(rm0, __shfl_xor_sync(0xffffffffu, rm0, 2));
            rm1 = fmaxf(rm1, __shfl_xor_sync(0xffffffffu, rm1, 1));
            rm1 = fmaxf(rm1, __shfl_xor_sync(0xffffffffu, rm1, 2));
            float mn0 = fmaxf(m0, rm0), mn1 = fmaxf(m1, rm1);
            float al0 = expf(m0 - mn0),  al1 = expf(m1 - mn1);
            m0 = mn0; m1 = mn1;

            float ps0 = 0.0f, ps1 = 0.0f;
            #pragma unroll
            for (int j = 0; j < 8; j++) {
                S[j][0] = expf(S[j][0] - m0);
                S[j][1] = expf(S[j][1] - m0);
                S[j][2] = expf(S[j][2] - m1);
                S[j][3] = expf(S[j][3] - m1);
                ps0 += S[j][0] + S[j][1];
                ps1 += S[j][2] + S[j][3];
            }
            l0 = l0 * al0 + ps0;
            l1 = l1 * al1 + ps1;
            #pragma unroll
            for (int j = 0; j < 8; j++) {
                o[j][0] *= al0; o[j][1] *= al0;
                o[j][2] *= al1; o[j][3] *= al1;
            }

            // ---- O += P.V (P split in registers) ----
            #pragma unroll
            for (int j = 0; j < 4; j++) {
                uint32_t ph[4], pl[4];
                split2(S[2*j  ][0], S[2*j  ][1], ph[0], pl[0]);
                split2(S[2*j  ][2], S[2*j  ][3], ph[1], pl[1]);
                split2(S[2*j+1][0], S[2*j+1][1], ph[2], pl[2]);
                split2(S[2*j+1][2], S[2*j+1][3], ph[3], pl[3]);
                #pragma unroll
                for (int pp = 0; pp < 4; pp++) {
                    uint32_t vh[4], vl[4];
                    uint32_t voff = (uint32_t)((j * 16 + (lane & 15)) * FTSTR
                                               + pp * 16 + ((lane >> 4) << 3)) * 2;
                    LDMX4T(vh[0], vh[1], vh[2], vh[3], stb + FV_H + voff);
                    LDMX4T(vl[0], vl[1], vl[2], vl[3], stb + FV_L + voff);
                    MMA16816(o[pp*2+0], ph, vh[0], vh[1]);
                    MMA16816(o[pp*2+1], ph, vh[2], vh[3]);
                    MMA16816(o[pp*2+0], ph, vl[0], vl[1]);
                    MMA16816(o[pp*2+1], ph, vl[2], vl[3]);
                    MMA16816(o[pp*2+0], pl, vh[0], vh[1]);
                    MMA16816(o[pp*2+1], pl, vh[2], vh[3]);
                }
            }
        }
        __syncthreads();
    }

    // ---- finalize ----
    l0 += __shfl_xor_sync(0xffffffffu, l0, 1);
    l0 += __shfl_xor_sync(0xffffffffu, l0, 2);
    l1 += __shfl_xor_sync(0xffffffffu, l1, 1);
    l1 += __shfl_xor_sync(0xffffffffu, l1, 2);
    float i0 = 1.0f / l0, i1 = 1.0f / l1;

    size_t gr0 = (size_t)b * SSEQ + q0 + w * 16 + (lane >> 2);
    #pragma unroll
    for (int j = 0; j < 8; j++) {
        int col = h * HD + j * 8 + (lane & 3) * 2;
        uint32_t uh, ul;
        split2(o[j][0] * i0, o[j][1] * i0, uh, ul);
        *(uint32_t*)(Ohi + gr0 * DD + col) = uh;
        *(uint32_t*)(Olo + gr0 * DD + col) = ul;
        split2(o[j][2] * i1, o[j][3] * i1, uh, ul);
        *(uint32_t*)(Ohi + (gr0 + 8) * DD + col) = uh;
        *(uint32_t*)(Olo + (gr0 + 8) * DD + col) = ul;
    }
}

// ---------------- host orchestration ---------------------------------------
extern "C" void kernel_launch(void* const* d_in, const int* in_sizes, int n_in,
                              void* d_out, int out_size)
{
    const float *ts, *fg, *fb, *wq, *bq, *wkv, *bkv, *wo, *bo,
                *w1, *b1, *w2, *b2, *ag, *ab, *ffg, *ffb;
    if (in_sizes[1] == 1024) {
        ts  = (const float*)d_in[0];
        fg  = (const float*)d_in[1];  fb  = (const float*)d_in[2];
        wq  = (const float*)d_in[3];  bq  = (const float*)d_in[4];
        wkv = (const float*)d_in[5];  bkv = (const float*)d_in[6];
        wo  = (const float*)d_in[7];  bo  = (const float*)d_in[8];
        w1  = (const float*)d_in[9];  b1  = (const float*)d_in[10];
        w2  = (const float*)d_in[11]; b2  = (const float*)d_in[12];
        ag  = (const float*)d_in[13]; ab  = (const float*)d_in[14];
        ffg = (const float*)d_in[15]; ffb = (const float*)d_in[16];
    } else {
        ts  = (const float*)d_in[0];
        wq  = (const float*)d_in[1];  bq  = (const float*)d_in[2];
        wkv = (const float*)d_in[3];  bkv = (const float*)d_in[4];
        wo  = (const float*)d_in[5];  bo  = (const float*)d_in[6];
        w1  = (const float*)d_in[7];  b1  = (const float*)d_in[8];
        w2  = (const float*)d_in[9];  b2  = (const float*)d_in[10];
        ag  = (const float*)d_in[11]; ab  = (const float*)d_in[12];
        ffg = (const float*)d_in[13]; ffb = (const float*)d_in[14];
        fg  = (const float*)d_in[15]; fb  = (const float*)d_in[16];
    }

    float *x;
    __nv_bfloat16 *hh, *hl, *qh_, *ql_, *kvh, *kvl, *ath, *atl, *fh, *fl;
    __nv_bfloat16 *wqh, *wql, *wkvh, *wkvl, *woh, *wol, *w1h, *w1l, *w2h, *w2l;
    cudaGetSymbolAddress((void**)&x,    g_x);
    cudaGetSymbolAddress((void**)&hh,   g_h_hi);
    cudaGetSymbolAddress((void**)&hl,   g_h_lo);
    cudaGetSymbolAddress((void**)&qh_,  g_q_hi);
    cudaGetSymbolAddress((void**)&ql_,  g_q_lo);
    cudaGetSymbolAddress((void**)&kvh,  g_kv_hi);
    cudaGetSymbolAddress((void**)&kvl,  g_kv_lo);
    cudaGetSymbolAddress((void**)&ath,  g_att_hi);
    cudaGetSymbolAddress((void**)&atl,  g_att_lo);
    cudaGetSymbolAddress((void**)&fh,   g_f_hi);
    cudaGetSymbolAddress((void**)&fl,   g_f_lo);
    cudaGetSymbolAddress((void**)&wqh,  g_wq_h);
    cudaGetSymbolAddress((void**)&wql,  g_wq_l);
    cudaGetSymbolAddress((void**)&wkvh, g_wkv_h);
    cudaGetSymbolAddress((void**)&wkvl, g_wkv_l);
    cudaGetSymbolAddress((void**)&woh,  g_wo_h);
    cudaGetSymbolAddress((void**)&wol,  g_wo_l);
    cudaGetSymbolAddress((void**)&w1h,  g_w1_h);
    cudaGetSymbolAddress((void**)&w1l,  g_w1_l);
    cudaGetSymbolAddress((void**)&w2h,  g_w2_h);
    cudaGetSymbolAddress((void**)&w2l,  g_w2_l);

    cudaFuncSetAttribute(tgemm_kernel,
                         cudaFuncAttributeMaxDynamicSharedMemorySize, TG_SMEM);
    cudaFuncSetAttribute(fattn_kernel,
                         cudaFuncAttributeMaxDynamicSharedMemorySize, F_SMEM);

    cudaMemcpyAsync(x, ts, sizeof(float) * (size_t)NT * DD,
                    cudaMemcpyDeviceToDevice, 0);

    // weight transpose + split: all layers per weight type (grid.z = NL)
    {
        dim3 blk(32, 8);
        wconv_kernel<<<dim3(DD/32, DD/32, NL), blk>>>(wq,  wqh,  wql,  DD, DD);
        wconv_kernel<<<dim3(2*DD/32, DD/32, NL), blk>>>(wkv, wkvh, wkvl, DD, 2*DD);
        wconv_kernel<<<dim3(DD/32, DD/32, NL), blk>>>(wo,  woh,  wol,  DD, DD);
        wconv_kernel<<<dim3(FF/32, DD/32, NL), blk>>>(w1,  w1h,  w1l,  DD, FF);
        wconv_kernel<<<dim3(DD/32, FF/32, NL), blk>>>(w2,  w2h,  w2l,  FF, DD);
    }

    for (int l = 0; l < NL; l++) {
        ln_bf16_kernel<<<NT, 256>>>(x, ag + (size_t)l*DD, ab + (size_t)l*DD, hh, hl);
        tgemm_kernel<<<dim3(DD/64, NT/128), 256, TG_SMEM>>>(
            hh, hl, wqh + (size_t)l*DD*DD, wql + (size_t)l*DD*DD,
            bq + (size_t)l*DD, nullptr, nullptr, qh_, ql_, DD, DD, 3, 0.125f);
        tgemm_kernel<<<dim3(2*DD/64, NT/128), 256, TG_SMEM>>>(
            hh, hl, wkvh + (size_t)l*DD*2*DD, wkvl + (size_t)l*DD*2*DD,
            bkv + (size_t)l*2*DD, nullptr, nullptr, kvh, kvl, DD, 2*DD, 3, 1.0f);
        fattn_kernel<<<dim3(SSEQ/128, BB*HH), 256, F_SMEM>>>(
            qh_, ql_, kvh, kvl, ath, atl);
        tgemm_kernel<<<dim3(DD/64, NT/128), 256, TG_SMEM>>>(
            ath, atl, woh + (size_t)l*DD*DD, wol + (size_t)l*DD*DD,
            bo + (size_t)l*DD, x, x, nullptr, nullptr, DD, DD, 2, 1.0f);
        ln_bf16_kernel<<<NT, 256>>>(x, ffg + (size_t)l*DD, ffb + (size_t)l*DD, hh, hl);
        tgemm_kernel<<<dim3(FF/64, NT/128), 256, TG_SMEM>>>(
            hh, hl, w1h + (size_t)l*DD*FF, w1l + (size_t)l*DD*FF,
            b1 + (size_t)l*FF, nullptr, nullptr, fh, fl, DD, FF, 1, 1.0f);
        tgemm_kernel<<<dim3(DD/64, NT/128), 256, TG_SMEM>>>(
            fh, fl, w2h + (size_t)l*FF*DD, w2l + (size_t)l*FF*DD,
            b2 + (size_t)l*DD, x, x, nullptr, nullptr, FF, DD, 2, 1.0f);
    }

    ln_kernel<<<NT, 256>>>(x, fg, fb, (float*)d_out);
}

// round 11
// speedup vs baseline: 2.5729x; 1.0059x over previous
#include <cuda_runtime.h>
#include <cuda_bf16.h>
#include <math.h>
#include <stdint.h>

// Problem constants
#define BB 2
#define SSEQ 2048
#define DD 1024
#define HH 16
#define HD 64
#define FF 4096
#define NL 8
#define NT (BB*SSEQ)   // 4096 token rows

// ---------------- scratch (device globals: allocation-guard safe) ----------
__device__ float g_x  [NT*DD];            // residual stream fp32

__device__ __nv_bfloat16 g_h_hi [NT*DD];  // LN out split
__device__ __nv_bfloat16 g_h_lo [NT*DD];
__device__ __nv_bfloat16 g_q_hi [NT*DD];  // Q split (pre-scaled by 1/8)
__device__ __nv_bfloat16 g_q_lo [NT*DD];
__device__ __nv_bfloat16 g_kv_hi[NT*2*DD];// K|V split
__device__ __nv_bfloat16 g_kv_lo[NT*2*DD];
__device__ __nv_bfloat16 g_att_hi[NT*DD]; // attention heads split
__device__ __nv_bfloat16 g_att_lo[NT*DD];
__device__ __nv_bfloat16 g_f_hi [NT*FF];  // FFN hidden split
__device__ __nv_bfloat16 g_f_lo [NT*FF];

// transposed+split weights, [out][in] K-major bf16
__device__ __nv_bfloat16 g_wqkv_h[NL*3*DD*DD];  // wq rows 0..1023, wkv rows 1024..3071
__device__ __nv_bfloat16 g_wqkv_l[NL*3*DD*DD];
__device__ __nv_bfloat16 g_wo_h [NL*DD*DD];
__device__ __nv_bfloat16 g_wo_l [NL*DD*DD];
__device__ __nv_bfloat16 g_w1_h [NL*DD*FF];
__device__ __nv_bfloat16 g_w1_l [NL*DD*FF];
__device__ __nv_bfloat16 g_w2_h [NL*FF*DD];
__device__ __nv_bfloat16 g_w2_l [NL*FF*DD];

// ---------------- small helpers --------------------------------------------
__device__ __forceinline__ float softplus_f(float x) {
    return fmaxf(x, 0.0f) + log1pf(expf(-fabsf(x)));
}
__device__ __forceinline__ uint32_t smem_u32(const void* p) {
    uint32_t a;
    asm("{ .reg .u64 t; cvta.to.shared.u64 t, %1; cvt.u32.u64 %0, t; }"
        : "=r"(a) : "l"(p));
    return a;
}
__device__ __forceinline__ void cp16(uint32_t s, const void* g) {
    asm volatile("cp.async.cg.shared.global [%0], [%1], 16;" :: "r"(s), "l"(g));
}
#define CP_COMMIT() asm volatile("cp.async.commit_group;")
#define CP_WAIT0()  asm volatile("cp.async.wait_group 0;")
#define CP_WAIT1()  asm volatile("cp.async.wait_group 1;")

// split fp32 into hi/lo bf16 pair packed as bf16x2 words
__device__ __forceinline__ void split2(float a, float b, uint32_t& hi, uint32_t& lo) {
    __nv_bfloat162 h = __floats2bfloat162_rn(a, b);
    float ra = a - __bfloat162float(h.x);
    float rb = b - __bfloat162float(h.y);
    __nv_bfloat162 l = __floats2bfloat162_rn(ra, rb);
    hi = *(uint32_t*)&h;
    lo = *(uint32_t*)&l;
}

#define LDMX4(R0,R1,R2,R3,ADDR) \
    asm volatile("ldmatrix.sync.aligned.m8n8.x4.shared.b16 {%0,%1,%2,%3}, [%4];" \
        : "=r"(R0),"=r"(R1),"=r"(R2),"=r"(R3) : "r"(ADDR))

#define LDMX4T(R0,R1,R2,R3,ADDR) \
    asm volatile("ldmatrix.sync.aligned.m8n8.x4.trans.shared.b16 {%0,%1,%2,%3}, [%4];" \
        : "=r"(R0),"=r"(R1),"=r"(R2),"=r"(R3) : "r"(ADDR))

#define MMA16816(C, A, B0, B1) \
    asm volatile("mma.sync.aligned.m16n8k16.row.col.f32.bf16.bf16.f32 " \
        "{%0,%1,%2,%3}, {%4,%5,%6,%7}, {%8,%9}, {%0,%1,%2,%3};" \
        : "+f"((C)[0]),"+f"((C)[1]),"+f"((C)[2]),"+f"((C)[3]) \
        : "r"((A)[0]),"r"((A)[1]),"r"((A)[2]),"r"((A)[3]), "r"(B0),"r"(B1))

// ---------------- weight transpose + split: W[K,M] -> Wt_hi/lo[M,K] --------
// per-layer input stride K*M, per-layer OUTPUT stride ostride (row offset obase)
__global__ void wconv_kernel(const float* __restrict__ W,
                             __nv_bfloat16* __restrict__ oh,
                             __nv_bfloat16* __restrict__ ol,
                             int K, int M, size_t ostride)
{
    W  += (size_t)blockIdx.z * K * M;
    oh += (size_t)blockIdx.z * ostride;
    ol += (size_t)blockIdx.z * ostride;
    __shared__ float t[32][33];
    int m0 = blockIdx.x * 32, k0 = blockIdx.y * 32;
    int tx = threadIdx.x, ty = threadIdx.y;  // 32 x 8
    #pragma unroll
    for (int j = 0; j < 4; j++)
        t[ty + 8 * j][tx] = W[(size_t)(k0 + ty + 8 * j) * M + m0 + tx];
    __syncthreads();
    #pragma unroll
    for (int j = 0; j < 4; j++) {
        float v = t[tx][ty + 8 * j];
        int m = m0 + ty + 8 * j, k = k0 + tx;
        __nv_bfloat16 h = __float2bfloat16(v);
        oh[(size_t)m * K + k] = h;
        ol[(size_t)m * K + k] = __float2bfloat16(v - __bfloat162float(h));
    }
}

// ---------------- LayerNorm (fp32 out) --------------------------------------
__global__ void ln_kernel(const float* __restrict__ in,
                          const float* __restrict__ gamma,
                          const float* __restrict__ beta,
                          float* __restrict__ out)
{
    int row = blockIdx.x;
    int tid = threadIdx.x;
    const float* p = in + (size_t)row * DD;
    float4 v = *(const float4*)(p + tid * 4);
    float s  = v.x + v.y + v.z + v.w;
    float sq = v.x*v.x + v.y*v.y + v.z*v.z + v.w*v.w;
    __shared__ float sm1[8], sm2[8];
    #pragma unroll
    for (int o = 16; o > 0; o >>= 1) {
        s  += __shfl_xor_sync(0xffffffffu, s,  o);
        sq += __shfl_xor_sync(0xffffffffu, sq, o);
    }
    if ((tid & 31) == 0) { sm1[tid >> 5] = s; sm2[tid >> 5] = sq; }
    __syncthreads();
    if (tid < 32) {
        s  = (tid < 8) ? sm1[tid] : 0.0f;
        sq = (tid < 8) ? sm2[tid] : 0.0f;
        #pragma unroll
        for (int o = 4; o > 0; o >>= 1) {
            s  += __shfl_xor_sync(0xffffffffu, s,  o);
            sq += __shfl_xor_sync(0xffffffffu, sq, o);
        }
        if (tid == 0) { sm1[0] = s; sm2[0] = sq; }
    }
    __syncthreads();
    float mean = sm1[0] * (1.0f / DD);
    float var  = sm2[0] * (1.0f / DD) - mean * mean;
    float rs   = rsqrtf(var + 1e-3f);
    float4 g  = *(const float4*)(gamma + tid * 4);
    float4 be = *(const float4*)(beta  + tid * 4);
    float4 o4;
    o4.x = (v.x - mean) * rs * g.x + be.x;
    o4.y = (v.y - mean) * rs * g.y + be.y;
    o4.z = (v.z - mean) * rs * g.z + be.z;
    o4.w = (v.w - mean) * rs * g.w + be.w;
    *(float4*)(out + (size_t)row * DD + tid * 4) = o4;
}

// ---------------- LayerNorm (bf16 hi/lo out) --------------------------------
__global__ void ln_bf16_kernel(const float* __restrict__ in,
                               const float* __restrict__ gamma,
                               const float* __restrict__ beta,
                               __nv_bfloat16* __restrict__ ohi,
                               __nv_bfloat16* __restrict__ olo)
{
    int row = blockIdx.x;
    int tid = threadIdx.x;
    const float* p = in + (size_t)row * DD;
    float4 v = *(const float4*)(p + tid * 4);
    float s  = v.x + v.y + v.z + v.w;
    float sq = v.x*v.x + v.y*v.y + v.z*v.z + v.w*v.w;
    __shared__ float sm1[8], sm2[8];
    #pragma unroll
    for (int o = 16; o > 0; o >>= 1) {
        s  += __shfl_xor_sync(0xffffffffu, s,  o);
        sq += __shfl_xor_sync(0xffffffffu, sq, o);
    }
    if ((tid & 31) == 0) { sm1[tid >> 5] = s; sm2[tid >> 5] = sq; }
    __syncthreads();
    if (tid < 32) {
        s  = (tid < 8) ? sm1[tid] : 0.0f;
        sq = (tid < 8) ? sm2[tid] : 0.0f;
        #pragma unroll
        for (int o = 4; o > 0; o >>= 1) {
            s  += __shfl_xor_sync(0xffffffffu, s,  o);
            sq += __shfl_xor_sync(0xffffffffu, sq, o);
        }
        if (tid == 0) { sm1[0] = s; sm2[0] = sq; }
    }
    __syncthreads();
    float mean = sm1[0] * (1.0f / DD);
    float var  = sm2[0] * (1.0f / DD) - mean * mean;
    float rs   = rsqrtf(var + 1e-3f);
    float4 g  = *(const float4*)(gamma + tid * 4);
    float4 be = *(const float4*)(beta  + tid * 4);
    float a = (v.x - mean) * rs * g.x + be.x;
    float b = (v.y - mean) * rs * g.y + be.y;
    float c = (v.z - mean) * rs * g.z + be.z;
    float d = (v.w - mean) * rs * g.w + be.w;
    uint2 uh, ul;
    split2(a, b, uh.x, ul.x);
    split2(c, d, uh.y, ul.y);
    size_t off = (size_t)row * DD + tid * 4;
    *(uint2*)(ohi + off) = uh;
    *(uint2*)(olo + off) = ul;
}

// ---------------- HMMA split-bf16 GEMM, 128x128 tile, cp.async 2-stage ------
// C[NT, M] = A[NT, K] @ B[M, K]^T (+bias), K chunks of 64.
// Block: 128 rows x 128 cols, 8 warps (4m x 2n), warp tile 32x64.
// epi: 1 = bias+softplus -> bf16 hi/lo (stride M)
//      2 = bias+res -> fp32 C (stride M)
//      4 = merged QKV: col<DD -> (*0.125) -> Chi/Clo (stride DD) w/ bias
//                      col>=DD -> Chi2/Clo2 (stride 2DD) w/ bias2
#define TSTR 72                      // smem row stride in bf16 elems (144 B)
#define SA_H 0
#define SA_L 18432                   // 128*72*2
#define SB_H 36864
#define SB_L 55296
#define TG_STAGE 73728
#define TG_SMEM (2*TG_STAGE)         // 147456

#define TG_LOADS(kb, stg) do {                                            \
    uint32_t base_ = sb + (uint32_t)(stg) * TG_STAGE;                     \
    _Pragma("unroll")                                                     \
    for (int u = 0; u < 4; u++) {                                         \
        int idx = tid + u * 256;                                          \
        int r = idx >> 3, c = (idx & 7) * 8;                              \
        size_t g = (size_t)(m0 + r) * K + (kb) + c;                       \
        uint32_t so = (uint32_t)(r * TSTR + c) * 2;                       \
        cp16(base_ + SA_H + so, Ah + g);                                  \
        cp16(base_ + SA_L + so, Al + g);                                  \
        size_t gb = (size_t)(n0 + r) * K + (kb) + c;                      \
        cp16(base_ + SB_H + so, Bh + gb);                                 \
        cp16(base_ + SB_L + so, Bl + gb);                                 \
    }                                                                     \
} while (0)

__global__ void __launch_bounds__(256) tgemm_kernel(
    const __nv_bfloat16* __restrict__ Ah, const __nv_bfloat16* __restrict__ Al,
    const __nv_bfloat16* __restrict__ Bh, const __nv_bfloat16* __restrict__ Bl,
    const float* __restrict__ bias, const float* __restrict__ bias2,
    const float* __restrict__ res,
    float* __restrict__ C, __nv_bfloat16* __restrict__ Chi,
    __nv_bfloat16* __restrict__ Clo, __nv_bfloat16* __restrict__ Chi2,
    __nv_bfloat16* __restrict__ Clo2, int K, int M, int epi)
{
    extern __shared__ char smem[];
    uint32_t sb = smem_u32(smem);
    int tid  = threadIdx.x;
    int lane = tid & 31;
    int w    = tid >> 5;
    int wm   = w & 3;            // 0..3 -> 32-row group
    int wn   = w >> 2;           // 0..1 -> 64-col group

    int m0 = blockIdx.y * 128;
    int n0 = blockIdx.x * 128;

    float acc[2][8][4];
    #pragma unroll
    for (int i = 0; i < 2; i++)
        #pragma unroll
        for (int j = 0; j < 8; j++)
            #pragma unroll
            for (int c = 0; c < 4; c++) acc[i][j][c] = 0.0f;

    uint32_t a_off = (uint32_t)((wm * 32 + (lane & 15)) * TSTR + ((lane >> 4) << 3)) * 2;
    uint32_t b_off = (uint32_t)((wn * 64 + ((lane >> 4) << 3) + (lane & 7)) * TSTR
                                + (((lane >> 3) & 1) << 3)) * 2;

    int nch = K >> 6;
    TG_LOADS(0, 0);
    CP_COMMIT();

    for (int kc = 0; kc < nch; kc++) {
        if (kc + 1 < nch) {
            TG_LOADS((kc + 1) * 64, (kc + 1) & 1);
            CP_COMMIT();
            CP_WAIT1();
        } else {
            CP_WAIT0();
        }
        __syncthreads();

        uint32_t stb = sb + (uint32_t)(kc & 1) * TG_STAGE;
        #pragma unroll
        for (int ks = 0; ks < 4; ks++) {
            uint32_t kb = (uint32_t)(ks * 16) * 2;
            uint32_t ah[2][4], al[2][4];
            #pragma unroll
            for (int i = 0; i < 2; i++) {
                uint32_t aa = stb + SA_H + a_off + (uint32_t)(i * 16 * TSTR) * 2 + kb;
                LDMX4(ah[i][0], ah[i][1], ah[i][2], ah[i][3], aa);
                uint32_t aa2 = stb + SA_L + a_off + (uint32_t)(i * 16 * TSTR) * 2 + kb;
                LDMX4(al[i][0], al[i][1], al[i][2], al[i][3], aa2);
            }
            #pragma unroll
            for (int p = 0; p < 4; p++) {
                uint32_t bh[4], bl[4];
                uint32_t ba = stb + SB_H + b_off + (uint32_t)(p * 16 * TSTR) * 2 + kb;
                LDMX4(bh[0], bh[1], bh[2], bh[3], ba);
                uint32_t ba2 = stb + SB_L + b_off + (uint32_t)(p * 16 * TSTR) * 2 + kb;
                LDMX4(bl[0], bl[1], bl[2], bl[3], ba2);
                #pragma unroll
                for (int i = 0; i < 2; i++)
                    #pragma unroll
                    for (int sub = 0; sub < 2; sub++) {
                        int j = p * 2 + sub;
                        MMA16816(acc[i][j], ah[i], bh[sub * 2], bh[sub * 2 + 1]);
                        MMA16816(acc[i][j], ah[i], bl[sub * 2], bl[sub * 2 + 1]);
                        MMA16816(acc[i][j], al[i], bh[sub * 2], bh[sub * 2 + 1]);
                    }
            }
        }
        __syncthreads();
    }

    // ---- epilogue ----
    #pragma unroll
    for (int i = 0; i < 2; i++) {
        int row0 = m0 + wm * 32 + i * 16 + (lane >> 2);
        #pragma unroll
        for (int j = 0; j < 8; j++) {
            int pp = j >> 1, sub = j & 1;
            int col = n0 + wn * 64 + pp * 16 + sub * 8 + (lane & 3) * 2;
            #pragma unroll
            for (int half = 0; half < 2; half++) {
                int r = row0 + half * 8;
                float o0 = acc[i][j][half * 2 + 0];
                float o1 = acc[i][j][half * 2 + 1];
                if (epi == 4) {
                    if (col < DD) {
                        float2 b2 = *(const float2*)(bias + col);
                        o0 = (o0 + b2.x) * 0.125f;
                        o1 = (o1 + b2.y) * 0.125f;
                        uint32_t uh, ul;
                        split2(o0, o1, uh, ul);
                        size_t off = (size_t)r * DD + col;
                        *(uint32_t*)(Chi + off) = uh;
                        *(uint32_t*)(Clo + off) = ul;
                    } else {
                        float2 b2 = *(const float2*)(bias2 + (col - DD));
                        o0 += b2.x; o1 += b2.y;
                        uint32_t uh, ul;
                        split2(o0, o1, uh, ul);
                        size_t off = (size_t)r * (2 * DD) + (col - DD);
                        *(uint32_t*)(Chi2 + off) = uh;
                        *(uint32_t*)(Clo2 + off) = ul;
                    }
                } else if (epi == 1) {
                    float2 b2 = *(const float2*)(bias + col);
                    o0 = softplus_f(o0 + b2.x);
                    o1 = softplus_f(o1 + b2.y);
                    uint32_t uh, ul;
                    split2(o0, o1, uh, ul);
                    size_t off = (size_t)r * M + col;
                    *(uint32_t*)(Chi + off) = uh;
                    *(uint32_t*)(Clo + off) = ul;
                } else {   // epi == 2
                    float2 b2 = *(const float2*)(bias + col);
                    size_t off = (size_t)r * M + col;
                    float2 r2 = *(const float2*)(res + off);
                    float2 o = {o0 + b2.x + r2.x, o1 + b2.y + r2.y};
                    *(float2*)(C + off) = o;
                }
            }
        }
    }
}

// ---------------- fused flash attention, cp.async K/V double buffer ---------
// grid (16 qtiles, 32 bh), 256 thr (8 warps x 16 q-rows).
#define FTSTR 72
#define FQ_H 0
#define FQ_L 18432
#define FKV0 36864                      // stage base; stage size 36864
#define FKV_STAGE 36864
#define FK_H 0
#define FK_L 9216
#define FV_H 18432
#define FV_L 27648
#define F_SMEM (FKV0 + 2*FKV_STAGE)     // 110592

#define F_LOADKV(kt, stg) do {                                            \
    uint32_t base_ = sb + FKV0 + (uint32_t)(stg) * FKV_STAGE;             \
    _Pragma("unroll")                                                     \
    for (int u = 0; u < 2; u++) {                                         \
        int idx = tid + u * 256;                                          \
        int r = idx >> 3, c = (idx & 7) * 8;                              \
        size_t gk = (size_t)((kt) * 64 + r) * (2 * DD) + c;               \
        uint32_t so = (uint32_t)(r * FTSTR + c) * 2;                      \
        cp16(base_ + FK_H + so, kb_h + gk);                               \
        cp16(base_ + FK_L + so, kb_l + gk);                               \
        cp16(base_ + FV_H + so, kb_h + gk + DD);                          \
        cp16(base_ + FV_L + so, kb_l + gk + DD);                          \
    }                                                                     \
} while (0)

__global__ void __launch_bounds__(256) fattn_kernel(
    const __nv_bfloat16* __restrict__ Qh_, const __nv_bfloat16* __restrict__ Ql_,
    const __nv_bfloat16* __restrict__ KVh, const __nv_bfloat16* __restrict__ KVl,
    __nv_bfloat16* __restrict__ Ohi, __nv_bfloat16* __restrict__ Olo)
{
    extern __shared__ char smem[];
    uint32_t sb = smem_u32(smem);
    int tid = threadIdx.x, lane = tid & 31, w = tid >> 5;
    int qtile = gridDim.x - 1 - blockIdx.x;   // heavy tiles first
    int bh = blockIdx.y;
    int b = bh >> 4, h = bh & 15;
    int q0 = qtile * 128;

    const __nv_bfloat16* kb_h = KVh + (size_t)b * SSEQ * 2 * DD + h * HD;
    const __nv_bfloat16* kb_l = KVl + (size_t)b * SSEQ * 2 * DD + h * HD;

    // prefetch K/V tile 0 while loading Q
    F_LOADKV(0, 0);
    CP_COMMIT();

    // ---- load Q tile (128 x 64) hi/lo ----
    #pragma unroll
    for (int u = 0; u < 4; u++) {
        int idx = tid + u * 256;
        int r = idx >> 3, c = (idx & 7) * 8;
        size_t g = ((size_t)b * SSEQ + q0 + r) * DD + h * HD + c;
        uint32_t so = (uint32_t)(r * FTSTR + c) * 2;
        *(uint4*)(smem + FQ_H + so) = *(const uint4*)(Qh_ + g);
        *(uint4*)(smem + FQ_L + so) = *(const uint4*)(Ql_ + g);
    }
    __syncthreads();

    uint32_t qh[4][4], ql[4][4];
    uint32_t a_off = (uint32_t)((w * 16 + (lane & 15)) * FTSTR + ((lane >> 4) << 3)) * 2;
    #pragma unroll
    for (int ks = 0; ks < 4; ks++) {
        LDMX4(qh[ks][0], qh[ks][1], qh[ks][2], qh[ks][3], sb + FQ_H + a_off + ks * 32);
        LDMX4(ql[ks][0], ql[ks][1], ql[ks][2], ql[ks][3], sb + FQ_L + a_off + ks * 32);
    }

    float m0 = -1e30f, m1 = -1e30f, l0 = 0.0f, l1 = 0.0f;
    float o[8][4];
    #pragma unroll
    for (int j = 0; j < 8; j++)
        #pragma unroll
        for (int c = 0; c < 4; c++) o[j][c] = 0.0f;

    float slope = exp2f(-0.5f * (float)(h + 1));
    int row0 = q0 + w * 16 + (lane >> 2);
    int warp_rmax = q0 + w * 16 + 15;
    int nkt = (q0 + 127) / 64 + 1;

    for (int kt = 0; kt < nkt; kt++) {
        if (kt + 1 < nkt) {
            F_LOADKV(kt + 1, (kt + 1) & 1);
            CP_COMMIT();
            CP_WAIT1();
        } else {
            CP_WAIT0();
        }
        __syncthreads();

        uint32_t stb = sb + FKV0 + (uint32_t)(kt & 1) * FKV_STAGE;

        if (kt * 64 <= warp_rmax) {
            // ---- S = Q.K^T ----
            float S[8][4];
            #pragma unroll
            for (int j = 0; j < 8; j++)
                #pragma unroll
                for (int c = 0; c < 4; c++) S[j][c] = 0.0f;

            #pragma unroll
            for (int ks = 0; ks < 4; ks++) {
                #pragma unroll
                for (int p = 0; p < 4; p++) {
                    uint32_t kh[4], kl[4];
                    uint32_t boff = (uint32_t)((p * 16 + ((lane >> 4) << 3) + (lane & 7)) * FTSTR
                                               + (((lane >> 3) & 1) << 3)) * 2 + ks * 32;
                    LDMX4(kh[0], kh[1], kh[2], kh[3], stb + FK_H + boff);
                    LDMX4(kl[0], kl[1], kl[2], kl[3], stb + FK_L + boff);
                    MMA16816(S[p*2+0], qh[ks], kh[0], kh[1]);
                    MMA16816(S[p*2+1], qh[ks], kh[2], kh[3]);
                    MMA16816(S[p*2+0], qh[ks], kl[0], kl[1]);
                    MMA16816(S[p*2+1], qh[ks], kl[2], kl[3]);
                    MMA16816(S[p*2+0], ql[ks], kh[0], kh[1]);
                    MMA16816(S[p*2+1], ql[ks], kh[2], kh[3]);
                }
            }

            // ---- alibi + causal mask ----
            #pragma unroll
            for (int j = 0; j < 8; j++) {
                int col = kt * 64 + j * 8 + (lane & 3) * 2;
                S[j][0] = (col     <= row0)     ? S[j][0] + slope * (float)(col     - row0)     : -1e30f;
                S[j][1] = (col + 1 <= row0)     ? S[j][1] + slope * (float)(col + 1 - row0)     : -1e30f;
                S[j][2] = (col     <= row0 + 8) ? S[j][2] + slope * (float)(col     - row0 - 8) : -1e30f;
                S[j][3] = (col + 1 <= row0 + 8) ? S[j][3] + slope * (float)(col + 1 - row0 - 8) : -1e30f;
            }

            // ---- online softmax update ----
            float rm0 = -1e30f, rm1 = -1e30f;
            #pragma unroll
            for (int j = 0; j < 8; j++) {
                rm0 = fmaxf(rm0, fmaxf(S[j][0], S[j][1]));
                rm1 = fmaxf(rm1, fmaxf(S[j][2], S[j][3]));
            }
            rm0 = fmaxf(rm0, __shfl_xor_sync(0xffffffffu, rm0, 1));
            rm0 = fmaxf(rm0, __shfl_xor_sync(0xffffffffu, rm0, 2));
            rm1 = fmaxf(rm1, __shfl_xor_sync(0xffffffffu, rm1, 1));
            rm1 = fmaxf(rm1, __shfl_xor_sync(0xffffffffu, rm1, 2));
            float mn0 = fmaxf(m0, rm0), mn1 = fmaxf(m1, rm1);
            float al0 = expf(m0 - mn0),  al1 = expf(m1 - mn1);
            m0 = mn0; m1 = mn1;

            float ps0 = 0.0f, ps1 = 0.0f;
            #pragma unroll
            for (int j = 0; j < 8; j++) {
                S[j][0] = expf(S[j][0] - m0);
                S[j][1] = expf(S[j][1] - m0);
                S[j][2] = expf(S[j][2] - m1);
                S[j][3] = expf(S[j][3] - m1);
                ps0 += S[j][0] + S[j][1];
                ps1 += S[j][2] + S[j][3];
            }
            l0 = l0 * al0 + ps0;
            l1 = l1 * al1 + ps1;
            #pragma unroll
            for (int j = 0; j < 8; j++) {
                o[j][0] *= al0; o[j][1] *= al0;
                o[j][2] *= al1; o[j][3] *= al1;
            }

            // ---- O += P.V (P split in registers) ----
            #pragma unroll
            for (int j = 0; j < 4; j++) {
                uint32_t ph[4], pl[4];
                split2(S[2*j  ][0], S[2*j  ][1], ph[0], pl[0]);
                split2(S[2*j  ][2], S[2*j  ][3], ph[1], pl[1]);
                split2(S[2*j+1][0], S[2*j+1][1], ph[2], pl[2]);
                split2(S[2*j+1][2], S[2*j+1][3], ph[3], pl[3]);
                #pragma unroll
                for (int pp = 0; pp < 4; pp++) {
                    uint32_t vh[4], vl[4];
                    uint32_t voff = (uint32_t)((j * 16 + (lane & 15)) * FTSTR
                                               + pp * 16 + ((lane >> 4) << 3)) * 2;
                    LDMX4T(vh[0], vh[1], vh[2], vh[3], stb + FV_H + voff);
                    LDMX4T(vl[0], vl[1], vl[2], vl[3], stb + FV_L + voff);
                    MMA16816(o[pp*2+0], ph, vh[0], vh[1]);
                    MMA16816(o[pp*2+1], ph, vh[2], vh[3]);
                    MMA16816(o[pp*2+0], ph, vl[0], vl[1]);
                    MMA16816(o[pp*2+1], ph, vl[2], vl[3]);
                    MMA16816(o[pp*2+0], pl, vh[0], vh[1]);
                    MMA16816(o[pp*2+1], pl, vh[2], vh[3]);
                }
            }
        }
        __syncthreads();
    }

    // ---- finalize ----
    l0 += __shfl_xor_sync(0xffffffffu, l0, 1);
    l0 += __shfl_xor_sync(0xffffffffu, l0, 2);
    l1 += __shfl_xor_sync(0xffffffffu, l1, 1);
    l1 += __shfl_xor_sync(0xffffffffu, l1, 2);
    float i0 = 1.0f / l0, i1 = 1.0f / l1;

    size_t gr0 = (size_t)b * SSEQ + q0 + w * 16 + (lane >> 2);
    #pragma unroll
    for (int j = 0; j < 8; j++) {
        int col = h * HD + j * 8 + (lane & 3) * 2;
        uint32_t uh, ul;
        split2(o[j][0] * i0, o[j][1] * i0, uh, ul);
        *(uint32_t*)(Ohi + gr0 * DD + col) = uh;
        *(uint32_t*)(Olo + gr0 * DD + col) = ul;
        split2(o[j][2] * i1, o[j][3] * i1, uh, ul);
        *(uint32_t*)(Ohi + (gr0 + 8) * DD + col) = uh;
        *(uint32_t*)(Olo + (gr0 + 8) * DD + col) = ul;
    }
}

// ---------------- host orchestration ---------------------------------------
extern "C" void kernel_launch(void* const* d_in, const int* in_sizes, int n_in,
                              void* d_out, int out_size)
{
    const float *ts, *fg, *fb, *wq, *bq, *wkv, *bkv, *wo, *bo,
                *w1, *b1, *w2, *b2, *ag, *ab, *ffg, *ffb;
    if (in_sizes[1] == 1024) {
        ts  = (const float*)d_in[0];
        fg  = (const float*)d_in[1];  fb  = (const float*)d_in[2];
        wq  = (const float*)d_in[3];  bq  = (const float*)d_in[4];
        wkv = (const float*)d_in[5];  bkv = (const float*)d_in[6];
        wo  = (const float*)d_in[7];  bo  = (const float*)d_in[8];
        w1  = (const float*)d_in[9];  b1  = (const float*)d_in[10];
        w2  = (const float*)d_in[11]; b2  = (const float*)d_in[12];
        ag  = (const float*)d_in[13]; ab  = (const float*)d_in[14];
        ffg = (const float*)d_in[15]; ffb = (const float*)d_in[16];
    } else {
        ts  = (const float*)d_in[0];
        wq  = (const float*)d_in[1];  bq  = (const float*)d_in[2];
        wkv = (const float*)d_in[3];  bkv = (const float*)d_in[4];
        wo  = (const float*)d_in[5];  bo  = (const float*)d_in[6];
        w1  = (const float*)d_in[7];  b1  = (const float*)d_in[8];
        w2  = (const float*)d_in[9];  b2  = (const float*)d_in[10];
        ag  = (const float*)d_in[11]; ab  = (const float*)d_in[12];
        ffg = (const float*)d_in[13]; ffb = (const float*)d_in[14];
        fg  = (const float*)d_in[15]; fb  = (const float*)d_in[16];
    }

    float *x;
    __nv_bfloat16 *hh, *hl, *qh_, *ql_, *kvh, *kvl, *ath, *atl, *fh, *fl;
    __nv_bfloat16 *wqkvh, *wqkvl, *woh, *wol, *w1h, *w1l, *w2h, *w2l;
    cudaGetSymbolAddress((void**)&x,    g_x);
    cudaGetSymbolAddress((void**)&hh,   g_h_hi);
    cudaGetSymbolAddress((void**)&hl,   g_h_lo);
    cudaGetSymbolAddress((void**)&qh_,  g_q_hi);
    cudaGetSymbolAddress((void**)&ql_,  g_q_lo);
    cudaGetSymbolAddress((void**)&kvh,  g_kv_hi);
    cudaGetSymbolAddress((void**)&kvl,  g_kv_lo);
    cudaGetSymbolAddress((void**)&ath,  g_att_hi);
    cudaGetSymbolAddress((void**)&atl,  g_att_lo);
    cudaGetSymbolAddress((void**)&fh,   g_f_hi);
    cudaGetSymbolAddress((void**)&fl,   g_f_lo);
    cudaGetSymbolAddress((void**)&wqkvh, g_wqkv_h);
    cudaGetSymbolAddress((void**)&wqkvl, g_wqkv_l);
    cudaGetSymbolAddress((void**)&woh,  g_wo_h);
    cudaGetSymbolAddress((void**)&wol,  g_wo_l);
    cudaGetSymbolAddress((void**)&w1h,  g_w1_h);
    cudaGetSymbolAddress((void**)&w1l,  g_w1_l);
    cudaGetSymbolAddress((void**)&w2h,  g_w2_h);
    cudaGetSymbolAddress((void**)&w2l,  g_w2_l);

    cudaFuncSetAttribute(tgemm_kernel,
                         cudaFuncAttributeMaxDynamicSharedMemorySize, TG_SMEM);
    cudaFuncSetAttribute(fattn_kernel,
                         cudaFuncAttributeMaxDynamicSharedMemorySize, F_SMEM);

    cudaMemcpyAsync(x, ts, sizeof(float) * (size_t)NT * DD,
                    cudaMemcpyDeviceToDevice, 0);

    // weight transpose + split: all layers per weight type (grid.z = NL)
    {
        dim3 blk(32, 8);
        // wq -> rows [0,1024) of packed wqkv ; wkv -> rows [1024,3072)
        wconv_kernel<<<dim3(DD/32, DD/32, NL), blk>>>(
            wq,  wqkvh,             wqkvl,             DD, DD,   (size_t)3*DD*DD);
        wconv_kernel<<<dim3(2*DD/32, DD/32, NL), blk>>>(
            wkv, wqkvh + DD*DD,     wqkvl + DD*DD,     DD, 2*DD, (size_t)3*DD*DD);
        wconv_kernel<<<dim3(DD/32, DD/32, NL), blk>>>(
            wo,  woh,  wol,  DD, DD, (size_t)DD*DD);
        wconv_kernel<<<dim3(FF/32, DD/32, NL), blk>>>(
            w1,  w1h,  w1l,  DD, FF, (size_t)DD*FF);
        wconv_kernel<<<dim3(DD/32, FF/32, NL), blk>>>(
            w2,  w2h,  w2l,  FF, DD, (size_t)FF*DD);
    }

    for (int l = 0; l < NL; l++) {
        ln_bf16_kernel<<<NT, 256>>>(x, ag + (size_t)l*DD, ab + (size_t)l*DD, hh, hl);
        // merged QKV GEMM: M = 3072, Q scaled 1/8 -> q buffers, KV -> kv buffers
        tgemm_kernel<<<dim3(3*DD/128, NT/128), 256, TG_SMEM>>>(
            hh, hl, wqkvh + (size_t)l*3*DD*DD, wqkvl + (size_t)l*3*DD*DD,
            bq + (size_t)l*DD, bkv + (size_t)l*2*DD, nullptr,
            nullptr, qh_, ql_, kvh, kvl, DD, 3*DD, 4);
        fattn_kernel<<<dim3(SSEQ/128, BB*HH), 256, F_SMEM>>>(
            qh_, ql_, kvh, kvl, ath, atl);
        // x = heads@wo + bo + x
        tgemm_kernel<<<dim3(DD/128, NT/128), 256, TG_SMEM>>>(
            ath, atl, woh + (size_t)l*DD*DD, wol + (size_t)l*DD*DD,
            bo + (size_t)l*DD, nullptr, x,
            x, nullptr, nullptr, nullptr, nullptr, DD, DD, 2);
        ln_bf16_kernel<<<NT, 256>>>(x, ffg + (size_t)l*DD, ffb + (size_t)l*DD, hh, hl);
        // f = softplus(h@w1 + b1) -> bf16 split
        tgemm_kernel<<<dim3(FF/128, NT/128), 256, TG_SMEM>>>(
            hh, hl, w1h + (size_t)l*DD*FF, w1l + (size_t)l*DD*FF,
            b1 + (size_t)l*FF, nullptr, nullptr,
            nullptr, fh, fl, nullptr, nullptr, DD, FF, 1);
        // x = f@w2 + b2 + x
        tgemm_kernel<<<dim3(DD/128, NT/128), 256, TG_SMEM>>>(
            fh, fl, w2h + (size_t)l*FF*DD, w2l + (size_t)l*FF*DD,
            b2 + (size_t)l*DD, nullptr, x,
            x, nullptr, nullptr, nullptr, nullptr, FF, DD, 2);
    }

    ln_kernel<<<NT, 256>>>(x, fg, fb, (float*)d_out);
}

// round 12
// speedup vs baseline: 2.5763x; 1.0013x over previous
#include <cuda_runtime.h>
#include <cuda_bf16.h>
#include <math.h>
#include <stdint.h>

// Problem constants
#define BB 2
#define SSEQ 2048
#define DD 1024
#define HH 16
#define HD 64
#define FF 4096
#define NL 8
#define NT (BB*SSEQ)   // 4096 token rows

// ---------------- scratch (device globals: allocation-guard safe) ----------
__device__ float g_x  [NT*DD];            // residual stream fp32

__device__ __nv_bfloat16 g_h_hi [NT*DD];  // LN out split
__device__ __nv_bfloat16 g_h_lo [NT*DD];
__device__ __nv_bfloat16 g_q_hi [NT*DD];  // Q split (pre-scaled by 1/8)
__device__ __nv_bfloat16 g_q_lo [NT*DD];
__device__ __nv_bfloat16 g_kv_hi[NT*2*DD];// K|V split
__device__ __nv_bfloat16 g_kv_lo[NT*2*DD];
__device__ __nv_bfloat16 g_att_hi[NT*DD]; // attention heads split
__device__ __nv_bfloat16 g_att_lo[NT*DD];
__device__ __nv_bfloat16 g_f_hi [NT*FF];  // FFN hidden split
__device__ __nv_bfloat16 g_f_lo [NT*FF];

// transposed+split weights, [out][in] K-major bf16
__device__ __nv_bfloat16 g_wqkv_h[NL*3*DD*DD];  // wq rows 0..1023, wkv rows 1024..3071
__device__ __nv_bfloat16 g_wqkv_l[NL*3*DD*DD];
__device__ __nv_bfloat16 g_wo_h [NL*DD*DD];
__device__ __nv_bfloat16 g_wo_l [NL*DD*DD];
__device__ __nv_bfloat16 g_w1_h [NL*DD*FF];
__device__ __nv_bfloat16 g_w1_l [NL*DD*FF];
__device__ __nv_bfloat16 g_w2_h [NL*FF*DD];
__device__ __nv_bfloat16 g_w2_l [NL*FF*DD];

// ---------------- small helpers --------------------------------------------
__device__ __forceinline__ float softplus_f(float x) {
    return fmaxf(x, 0.0f) + log1pf(expf(-fabsf(x)));
}
__device__ __forceinline__ uint32_t smem_u32(const void* p) {
    uint32_t a;
    asm("{ .reg .u64 t; cvta.to.shared.u64 t, %1; cvt.u32.u64 %0, t; }"
        : "=r"(a) : "l"(p));
    return a;
}
__device__ __forceinline__ void cp16(uint32_t s, const void* g) {
    asm volatile("cp.async.cg.shared.global [%0], [%1], 16;" :: "r"(s), "l"(g));
}
#define CP_COMMIT() asm volatile("cp.async.commit_group;")
#define CP_WAIT0()  asm volatile("cp.async.wait_group 0;")
#define CP_WAIT1()  asm volatile("cp.async.wait_group 1;")

// split fp32 into hi/lo bf16 pair packed as bf16x2 words
__device__ __forceinline__ void split2(float a, float b, uint32_t& hi, uint32_t& lo) {
    __nv_bfloat162 h = __floats2bfloat162_rn(a, b);
    float ra = a - __bfloat162float(h.x);
    float rb = b - __bfloat162float(h.y);
    __nv_bfloat162 l = __floats2bfloat162_rn(ra, rb);
    hi = *(uint32_t*)&h;
    lo = *(uint32_t*)&l;
}

#define LDMX4(R0,R1,R2,R3,ADDR) \
    asm volatile("ldmatrix.sync.aligned.m8n8.x4.shared.b16 {%0,%1,%2,%3}, [%4];" \
        : "=r"(R0),"=r"(R1),"=r"(R2),"=r"(R3) : "r"(ADDR))

#define LDMX4T(R0,R1,R2,R3,ADDR) \
    asm volatile("ldmatrix.sync.aligned.m8n8.x4.trans.shared.b16 {%0,%1,%2,%3}, [%4];" \
        : "=r"(R0),"=r"(R1),"=r"(R2),"=r"(R3) : "r"(ADDR))

#define MMA16816(C, A, B0, B1) \
    asm volatile("mma.sync.aligned.m16n8k16.row.col.f32.bf16.bf16.f32 " \
        "{%0,%1,%2,%3}, {%4,%5,%6,%7}, {%8,%9}, {%0,%1,%2,%3};" \
        : "+f"((C)[0]),"+f"((C)[1]),"+f"((C)[2]),"+f"((C)[3]) \
        : "r"((A)[0]),"r"((A)[1]),"r"((A)[2]),"r"((A)[3]), "r"(B0),"r"(B1))

// ---------------- weight transpose + split: W[K,M] -> Wt_hi/lo[M,K] --------
// per-layer input stride K*M, per-layer OUTPUT stride ostride (row offset obase)
__global__ void wconv_kernel(const float* __restrict__ W,
                             __nv_bfloat16* __restrict__ oh,
                             __nv_bfloat16* __restrict__ ol,
                             int K, int M, size_t ostride)
{
    W  += (size_t)blockIdx.z * K * M;
    oh += (size_t)blockIdx.z * ostride;
    ol += (size_t)blockIdx.z * ostride;
    __shared__ float t[32][33];
    int m0 = blockIdx.x * 32, k0 = blockIdx.y * 32;
    int tx = threadIdx.x, ty = threadIdx.y;  // 32 x 8
    #pragma unroll
    for (int j = 0; j < 4; j++)
        t[ty + 8 * j][tx] = W[(size_t)(k0 + ty + 8 * j) * M + m0 + tx];
    __syncthreads();
    #pragma unroll
    for (int j = 0; j < 4; j++) {
        float v = t[tx][ty + 8 * j];
        int m = m0 + ty + 8 * j, k = k0 + tx;
        __nv_bfloat16 h = __float2bfloat16(v);
        oh[(size_t)m * K + k] = h;
        ol[(size_t)m * K + k] = __float2bfloat16(v - __bfloat162float(h));
    }
}

// ---------------- LayerNorm (fp32 out) --------------------------------------
__global__ void ln_kernel(const float* __restrict__ in,
                          const float* __restrict__ gamma,
                          const float* __restrict__ beta,
                          float* __restrict__ out)
{
    int row = blockIdx.x;
    int tid = threadIdx.x;
    const float* p = in + (size_t)row * DD;
    float4 v = *(const float4*)(p + tid * 4);
    float s  = v.x + v.y + v.z + v.w;
    float sq = v.x*v.x + v.y*v.y + v.z*v.z + v.w*v.w;
    __shared__ float sm1[8], sm2[8];
    #pragma unroll
    for (int o = 16; o > 0; o >>= 1) {
        s  += __shfl_xor_sync(0xffffffffu, s,  o);
        sq += __shfl_xor_sync(0xffffffffu, sq, o);
    }
    if ((tid & 31) == 0) { sm1[tid >> 5] = s; sm2[tid >> 5] = sq; }
    __syncthreads();
    if (tid < 32) {
        s  = (tid < 8) ? sm1[tid] : 0.0f;
        sq = (tid < 8) ? sm2[tid] : 0.0f;
        #pragma unroll
        for (int o = 4; o > 0; o >>= 1) {
            s  += __shfl_xor_sync(0xffffffffu, s,  o);
            sq += __shfl_xor_sync(0xffffffffu, sq, o);
        }
        if (tid == 0) { sm1[0] = s; sm2[0] = sq; }
    }
    __syncthreads();
    float mean = sm1[0] * (1.0f / DD);
    float var  = sm2[0] * (1.0f / DD) - mean * mean;
    float rs   = rsqrtf(var + 1e-3f);
    float4 g  = *(const float4*)(gamma + tid * 4);
    float4 be = *(const float4*)(beta  + tid * 4);
    float4 o4;
    o4.x = (v.x - mean) * rs * g.x + be.x;
    o4.y = (v.y - mean) * rs * g.y + be.y;
    o4.z = (v.z - mean) * rs * g.z + be.z;
    o4.w = (v.w - mean) * rs * g.w + be.w;
    *(float4*)(out + (size_t)row * DD + tid * 4) = o4;
}

// ---------------- LayerNorm (bf16 hi/lo out) --------------------------------
__global__ void ln_bf16_kernel(const float* __restrict__ in,
                               const float* __restrict__ gamma,
                               const float* __restrict__ beta,
                               __nv_bfloat16* __restrict__ ohi,
                               __nv_bfloat16* __restrict__ olo)
{
    int row = blockIdx.x;
    int tid = threadIdx.x;
    const float* p = in + (size_t)row * DD;
    float4 v = *(const float4*)(p + tid * 4);
    float s  = v.x + v.y + v.z + v.w;
    float sq = v.x*v.x + v.y*v.y + v.z*v.z + v.w*v.w;
    __shared__ float sm1[8], sm2[8];
    #pragma unroll
    for (int o = 16; o > 0; o >>= 1) {
        s  += __shfl_xor_sync(0xffffffffu, s,  o);
        sq += __shfl_xor_sync(0xffffffffu, sq, o);
    }
    if ((tid & 31) == 0) { sm1[tid >> 5] = s; sm2[tid >> 5] = sq; }
    __syncthreads();
    if (tid < 32) {
        s  = (tid < 8) ? sm1[tid] : 0.0f;
        sq = (tid < 8) ? sm2[tid] : 0.0f;
        #pragma unroll
        for (int o = 4; o > 0; o >>= 1) {
            s  += __shfl_xor_sync(0xffffffffu, s,  o);
            sq += __shfl_xor_sync(0xffffffffu, sq, o);
        }
        if (tid == 0) { sm1[0] = s; sm2[0] = sq; }
    }
    __syncthreads();
    float mean = sm1[0] * (1.0f / DD);
    float var  = sm2[0] * (1.0f / DD) - mean * mean;
    float rs   = rsqrtf(var + 1e-3f);
    float4 g  = *(const float4*)(gamma + tid * 4);
    float4 be = *(const float4*)(beta  + tid * 4);
    float a = (v.x - mean) * rs * g.x + be.x;
    float b = (v.y - mean) * rs * g.y + be.y;
    float c = (v.z - mean) * rs * g.z + be.z;
    float d = (v.w - mean) * rs * g.w + be.w;
    uint2 uh, ul;
    split2(a, b, uh.x, ul.x);
    split2(c, d, uh.y, ul.y);
    size_t off = (size_t)row * DD + tid * 4;
    *(uint2*)(ohi + off) = uh;
    *(uint2*)(olo + off) = ul;
}

// ---------------- HMMA split-bf16 GEMM, 128x128 tile, cp.async 2-stage ------
// C[NT, M] = A[NT, K] @ B[M, K]^T (+bias), K chunks of 64.
// Block: 128 rows x 128 cols, 8 warps (4m x 2n), warp tile 32x64.
// epi: 1 = bias+softplus -> bf16 hi/lo (stride M)
//      2 = bias+res -> fp32 C (stride M)
//      4 = merged QKV: col<DD -> (*0.125) -> Chi/Clo (stride DD) w/ bias
//                      col>=DD -> Chi2/Clo2 (stride 2DD) w/ bias2
#define TSTR 72                      // smem row stride in bf16 elems (144 B)
#define SA_H 0
#define SA_L 18432                   // 128*72*2
#define SB_H 36864
#define SB_L 55296
#define TG_STAGE 73728
#define TG_SMEM (2*TG_STAGE)         // 147456

#define TG_LOADS(kb, stg) do {                                            \
    uint32_t base_ = sb + (uint32_t)(stg) * TG_STAGE;                     \
    _Pragma("unroll")                                                     \
    for (int u = 0; u < 4; u++) {                                         \
        int idx = tid + u * 256;                                          \
        int r = idx >> 3, c = (idx & 7) * 8;                              \
        size_t g = (size_t)(m0 + r) * K + (kb) + c;                       \
        uint32_t so = (uint32_t)(r * TSTR + c) * 2;                       \
        cp16(base_ + SA_H + so, Ah + g);                                  \
        cp16(base_ + SA_L + so, Al + g);                                  \
        size_t gb = (size_t)(n0 + r) * K + (kb) + c;                      \
        cp16(base_ + SB_H + so, Bh + gb);                                 \
        cp16(base_ + SB_L + so, Bl + gb);                                 \
    }                                                                     \
} while (0)

__global__ void __launch_bounds__(256) tgemm_kernel(
    const __nv_bfloat16* __restrict__ Ah, const __nv_bfloat16* __restrict__ Al,
    const __nv_bfloat16* __restrict__ Bh, const __nv_bfloat16* __restrict__ Bl,
    const float* __restrict__ bias, const float* __restrict__ bias2,
    const float* __restrict__ res,
    float* __restrict__ C, __nv_bfloat16* __restrict__ Chi,
    __nv_bfloat16* __restrict__ Clo, __nv_bfloat16* __restrict__ Chi2,
    __nv_bfloat16* __restrict__ Clo2, int K, int M, int epi)
{
    extern __shared__ char smem[];
    uint32_t sb = smem_u32(smem);
    int tid  = threadIdx.x;
    int lane = tid & 31;
    int w    = tid >> 5;
    int wm   = w & 3;            // 0..3 -> 32-row group
    int wn   = w >> 2;           // 0..1 -> 64-col group

    int m0 = blockIdx.y * 128;
    int n0 = blockIdx.x * 128;

    float acc[2][8][4];
    #pragma unroll
    for (int i = 0; i < 2; i++)
        #pragma unroll
        for (int j = 0; j < 8; j++)
            #pragma unroll
            for (int c = 0; c < 4; c++) acc[i][j][c] = 0.0f;

    uint32_t a_off = (uint32_t)((wm * 32 + (lane & 15)) * TSTR + ((lane >> 4) << 3)) * 2;
    uint32_t b_off = (uint32_t)((wn * 64 + ((lane >> 4) << 3) + (lane & 7)) * TSTR
                                + (((lane >> 3) & 1) << 3)) * 2;

    int nch = K >> 6;
    TG_LOADS(0, 0);
    CP_COMMIT();

    for (int kc = 0; kc < nch; kc++) {
        if (kc + 1 < nch) {
            TG_LOADS((kc + 1) * 64, (kc + 1) & 1);
            CP_COMMIT();
            CP_WAIT1();
        } else {
            CP_WAIT0();
        }
        __syncthreads();

        uint32_t stb = sb + (uint32_t)(kc & 1) * TG_STAGE;
        #pragma unroll
        for (int ks = 0; ks < 4; ks++) {
            uint32_t kb = (uint32_t)(ks * 16) * 2;
            uint32_t ah[2][4], al[2][4];
            #pragma unroll
            for (int i = 0; i < 2; i++) {
                uint32_t aa = stb + SA_H + a_off + (uint32_t)(i * 16 * TSTR) * 2 + kb;
                LDMX4(ah[i][0], ah[i][1], ah[i][2], ah[i][3], aa);
                uint32_t aa2 = stb + SA_L + a_off + (uint32_t)(i * 16 * TSTR) * 2 + kb;
                LDMX4(al[i][0], al[i][1], al[i][2], al[i][3], aa2);
            }
            #pragma unroll
            for (int p = 0; p < 4; p++) {
                uint32_t bh[4], bl[4];
                uint32_t ba = stb + SB_H + b_off + (uint32_t)(p * 16 * TSTR) * 2 + kb;
                LDMX4(bh[0], bh[1], bh[2], bh[3], ba);
                uint32_t ba2 = stb + SB_L + b_off + (uint32_t)(p * 16 * TSTR) * 2 + kb;
                LDMX4(bl[0], bl[1], bl[2], bl[3], ba2);
                #pragma unroll
                for (int i = 0; i < 2; i++)
                    #pragma unroll
                    for (int sub = 0; sub < 2; sub++) {
                        int j = p * 2 + sub;
                        MMA16816(acc[i][j], ah[i], bh[sub * 2], bh[sub * 2 + 1]);
                        MMA16816(acc[i][j], ah[i], bl[sub * 2], bl[sub * 2 + 1]);
                        MMA16816(acc[i][j], al[i], bh[sub * 2], bh[sub * 2 + 1]);
                    }
            }
        }
        __syncthreads();
    }

    // ---- epilogue ----
    #pragma unroll
    for (int i = 0; i < 2; i++) {
        int row0 = m0 + wm * 32 + i * 16 + (lane >> 2);
        #pragma unroll
        for (int j = 0; j < 8; j++) {
            int pp = j >> 1, sub = j & 1;
            int col = n0 + wn * 64 + pp * 16 + sub * 8 + (lane & 3) * 2;
            #pragma unroll
            for (int half = 0; half < 2; half++) {
                int r = row0 + half * 8;
                float o0 = acc[i][j][half * 2 + 0];
                float o1 = acc[i][j][half * 2 + 1];
                if (epi == 4) {
                    if (col < DD) {
                        float2 b2 = *(const float2*)(bias + col);
                        o0 = (o0 + b2.x) * 0.125f;
                        o1 = (o1 + b2.y) * 0.125f;
                        uint32_t uh, ul;
                        split2(o0, o1, uh, ul);
                        size_t off = (size_t)r * DD + col;
                        *(uint32_t*)(Chi + off) = uh;
                        *(uint32_t*)(Clo + off) = ul;
                    } else {
                        float2 b2 = *(const float2*)(bias2 + (col - DD));
                        o0 += b2.x; o1 += b2.y;
                        uint32_t uh, ul;
                        split2(o0, o1, uh, ul);
                        size_t off = (size_t)r * (2 * DD) + (col - DD);
                        *(uint32_t*)(Chi2 + off) = uh;
                        *(uint32_t*)(Clo2 + off) = ul;
                    }
                } else if (epi == 1) {
                    float2 b2 = *(const float2*)(bias + col);
                    o0 = softplus_f(o0 + b2.x);
                    o1 = softplus_f(o1 + b2.y);
                    uint32_t uh, ul;
                    split2(o0, o1, uh, ul);
                    size_t off = (size_t)r * M + col;
                    *(uint32_t*)(Chi + off) = uh;
                    *(uint32_t*)(Clo + off) = ul;
                } else {   // epi == 2
                    float2 b2 = *(const float2*)(bias + col);
                    size_t off = (size_t)r * M + col;
                    float2 r2 = *(const float2*)(res + off);
                    float2 o = {o0 + b2.x + r2.x, o1 + b2.y + r2.y};
                    *(float2*)(C + off) = o;
                }
            }
        }
    }
}

// ---------------- fused flash attention, cp.async K/V double buffer ---------
// grid (16 qtiles, 32 bh), 256 thr (8 warps x 16 q-rows).
#define FTSTR 72
#define FQ_H 0
#define FQ_L 18432
#define FKV0 36864                      // stage base; stage size 36864
#define FKV_STAGE 36864
#define FK_H 0
#define FK_L 9216
#define FV_H 18432
#define FV_L 27648
#define F_SMEM (FKV0 + 2*FKV_STAGE)     // 110592

#define F_LOADKV(kt, stg) do {                                            \
    uint32_t base_ = sb + FKV0 + (uint32_t)(stg) * FKV_STAGE;             \
    _Pragma("unroll")                                                     \
    for (int u = 0; u < 2; u++) {                                         \
        int idx = tid + u * 256;                                          \
        int r = idx >> 3, c = (idx & 7) * 8;                              \
        size_t gk = (size_t)((kt) * 64 + r) * (2 * DD) + c;               \
        uint32_t so = (uint32_t)(r * FTSTR + c) * 2;                      \
        cp16(base_ + FK_H + so, kb_h + gk);                               \
        cp16(base_ + FK_L + so, kb_l + gk);                               \
        cp16(base_ + FV_H + so, kb_h + gk + DD);                          \
        cp16(base_ + FV_L + so, kb_l + gk + DD);                          \
    }                                                                     \
} while (0)

__global__ void __launch_bounds__(256) fattn_kernel(
    const __nv_bfloat16* __restrict__ Qh_, const __nv_bfloat16* __restrict__ Ql_,
    const __nv_bfloat16* __restrict__ KVh, const __nv_bfloat16* __restrict__ KVl,
    __nv_bfloat16* __restrict__ Ohi, __nv_bfloat16* __restrict__ Olo)
{
    extern __shared__ char smem[];
    uint32_t sb = smem_u32(smem);
    int tid = threadIdx.x, lane = tid & 31, w = tid >> 5;
    int qtile = gridDim.x - 1 - blockIdx.x;   // heavy tiles first
    int bh = blockIdx.y;
    int b = bh >> 4, h = bh & 15;
    int q0 = qtile * 128;

    const __nv_bfloat16* kb_h = KVh + (size_t)b * SSEQ * 2 * DD + h * HD;
    const __nv_bfloat16* kb_l = KVl + (size_t)b * SSEQ * 2 * DD + h * HD;

    // prefetch K/V tile 0 while loading Q
    F_LOADKV(0, 0);
    CP_COMMIT();

    // ---- load Q tile (128 x 64) hi/lo ----
    #pragma unroll
    for (int u = 0; u < 4; u++) {
        int idx = tid + u * 256;
        int r = idx >> 3, c = (idx & 7) * 8;
        size_t g = ((size_t)b * SSEQ + q0 + r) * DD + h * HD + c;
        uint32_t so = (uint32_t)(r * FTSTR + c) * 2;
        *(uint4*)(smem + FQ_H + so) = *(const uint4*)(Qh_ + g);
        *(uint4*)(smem + FQ_L + so) = *(const uint4*)(Ql_ + g);
    }
    __syncthreads();

    uint32_t qh[4][4], ql[4][4];
    uint32_t a_off = (uint32_t)((w * 16 + (lane & 15)) * FTSTR + ((lane >> 4) << 3)) * 2;
    #pragma unroll
    for (int ks = 0; ks < 4; ks++) {
        LDMX4(qh[ks][0], qh[ks][1], qh[ks][2], qh[ks][3], sb + FQ_H + a_off + ks * 32);
        LDMX4(ql[ks][0], ql[ks][1], ql[ks][2], ql[ks][3], sb + FQ_L + a_off + ks * 32);
    }

    float m0 = -1e30f, m1 = -1e30f, l0 = 0.0f, l1 = 0.0f;
    float o[8][4];
    #pragma unroll
    for (int j = 0; j < 8; j++)
        #pragma unroll
        for (int c = 0; c < 4; c++) o[j][c] = 0.0f;

    float slope = exp2f(-0.5f * (float)(h + 1));
    int row0 = q0 + w * 16 + (lane >> 2);
    int warp_rmax = q0 + w * 16 + 15;
    int nkt = (q0 + 127) / 64 + 1;

    for (int kt = 0; kt < nkt; kt++) {
        if (kt + 1 < nkt) {
            F_LOADKV(kt + 1, (kt + 1) & 1);
            CP_COMMIT();
            CP_WAIT1();
        } else {
            CP_WAIT0();
        }
        __syncthreads();

        uint32_t stb = sb + FKV0 + (uint32_t)(kt & 1) * FKV_STAGE;

        if (kt * 64 <= warp_rmax) {
            // ---- S = Q.K^T ----
            float S[8][4];
            #pragma unroll
            for (int j = 0; j < 8; j++)
                #pragma unroll
                for (int c = 0; c < 4; c++) S[j][c] = 0.0f;

            #pragma unroll
            for (int ks = 0; ks < 4; ks++) {
                #pragma unroll
                for (int p = 0; p < 4; p++) {
                    uint32_t kh[4], kl[4];
                    uint32_t boff = (uint32_t)((p * 16 + ((lane >> 4) << 3) + (lane & 7)) * FTSTR
                                               + (((lane >> 3) & 1) << 3)) * 2 + ks * 32;
                    LDMX4(kh[0], kh[1], kh[2], kh[3], stb + FK_H + boff);
                    LDMX4(kl[0], kl[1], kl[2], kl[3], stb + FK_L + boff);
                    MMA16816(S[p*2+0], qh[ks], kh[0], kh[1]);
                    MMA16816(S[p*2+1], qh[ks], kh[2], kh[3]);
                    MMA16816(S[p*2+0], qh[ks], kl[0], kl[1]);
                    MMA16816(S[p*2+1], qh[ks], kl[2], kl[3]);
                    MMA16816(S[p*2+0], ql[ks], kh[0], kh[1]);
                    MMA16816(S[p*2+1], ql[ks], kh[2], kh[3]);
                }
            }

            // ---- alibi + causal mask ----
            #pragma unroll
            for (int j = 0; j < 8; j++) {
                int col = kt * 64 + j * 8 + (lane & 3) * 2;
                S[j][0] = (col     <= row0)     ? S[j][0] + slope * (float)(col     - row0)     : -1e30f;
                S[j][1] = (col + 1 <= row0)     ? S[j][1] + slope * (float)(col + 1 - row0)     : -1e30f;
                S[j][2] = (col     <= row0 + 8) ? S[j][2] + slope * (float)(col     - row0 - 8) : -1e30f;
                S[j][3] = (col + 1 <= row0 + 8) ? S[j][3] + slope * (float)(col + 1 - row0 - 8) : -1e30f;
            }

            // ---- online softmax update ----
            float rm0 = -1e30f, rm1 = -1e30f;
            #pragma unroll
            for (int j = 0; j < 8; j++) {
                rm0 = fmaxf(rm0, fmaxf(S[j][0], S[j][1]));
                rm1 = fmaxf(rm1, fmaxf(S[j][2], S[j][3]));
            }
            rm0 = fmaxf(rm0, __shfl_xor_sync(0xffffffffu, rm0, 1));
            rm0 = fmaxf(rm0, __shfl_xor_sync(0xffffffffu, rm0, 2));
            rm1 = fmaxf(rm1, __shfl_xor_sync(0xffffffffu, rm1, 1));
            rm1 = fmaxf(rm1, __shfl_xor_sync(0xffffffffu, rm1, 2));
            float mn0 = fmaxf(m0, rm0), mn1 = fmaxf(m1, rm1);
            float al0 = expf(m0 - mn0),  al1 = expf(m1 - mn1);
            m0 = mn0; m1 = mn1;

            float ps0 = 0.0f, ps1 = 0.0f;
            #pragma unroll
            for (int j = 0; j < 8; j++) {
                S[j][0] = expf(S[j][0] - m0);
                S[j][1] = expf(S[j][1] - m0);
                S[j][2] = expf(S[j][2] - m1);
                S[j][3] = expf(S[j][3] - m1);
                ps0 += S[j][0] + S[j][1];
                ps1 += S[j][2] + S[j][3];
            }
            l0 = l0 * al0 + ps0;
            l1 = l1 * al1 + ps1;
            #pragma unroll
            for (int j = 0; j < 8; j++) {
                o[j][0] *= al0; o[j][1] *= al0;
                o[j][2] *= al1; o[j][3] *= al1;
            }

            // ---- O += P.V (P split in registers) ----
            #pragma unroll
            for (int j = 0; j < 4; j++) {
                uint32_t ph[4], pl[4];
                split2(S[2*j  ][0], S[2*j  ][1], ph[0], pl[0]);
                split2(S[2*j  ][2], S[2*j  ][3], ph[1], pl[1]);
                split2(S[2*j+1][0], S[2*j+1][1], ph[2], pl[2]);
                split2(S[2*j+1][2], S[2*j+1][3], ph[3], pl[3]);
                #pragma unroll
                for (int pp = 0; pp < 4; pp++) {
                    uint32_t vh[4], vl[4];
                    uint32_t voff = (uint32_t)((j * 16 + (lane & 15)) * FTSTR
                                               + pp * 16 + ((lane >> 4) << 3)) * 2;
                    LDMX4T(vh[0], vh[1], vh[2], vh[3], stb + FV_H + voff);
                    LDMX4T(vl[0], vl[1], vl[2], vl[3], stb + FV_L + voff);
                    MMA16816(o[pp*2+0], ph, vh[0], vh[1]);
                    MMA16816(o[pp*2+1], ph, vh[2], vh[3]);
                    MMA16816(o[pp*2+0], ph, vl[0], vl[1]);
                    MMA16816(o[pp*2+1], ph, vl[2], vl[3]);
                    MMA16816(o[pp*2+0], pl, vh[0], vh[1]);
                    MMA16816(o[pp*2+1], pl, vh[2], vh[3]);
                }
            }
        }
        __syncthreads();
    }

    // ---- finalize ----
    l0 += __shfl_xor_sync(0xffffffffu, l0, 1);
    l0 += __shfl_xor_sync(0xffffffffu, l0, 2);
    l1 += __shfl_xor_sync(0xffffffffu, l1, 1);
    l1 += __shfl_xor_sync(0xffffffffu, l1, 2);
    float i0 = 1.0f / l0, i1 = 1.0f / l1;

    size_t gr0 = (size_t)b * SSEQ + q0 + w * 16 + (lane >> 2);
    #pragma unroll
    for (int j = 0; j < 8; j++) {
        int col = h * HD + j * 8 + (lane & 3) * 2;
        uint32_t uh, ul;
        split2(o[j][0] * i0, o[j][1] * i0, uh, ul);
        *(uint32_t*)(Ohi + gr0 * DD + col) = uh;
        *(uint32_t*)(Olo + gr0 * DD + col) = ul;
        split2(o[j][2] * i1, o[j][3] * i1, uh, ul);
        *(uint32_t*)(Ohi + (gr0 + 8) * DD + col) = uh;
        *(uint32_t*)(Olo + (gr0 + 8) * DD + col) = ul;
    }
}

// ---------------- host orchestration ---------------------------------------
extern "C" void kernel_launch(void* const* d_in, const int* in_sizes, int n_in,
                              void* d_out, int out_size)
{
    const float *ts, *fg, *fb, *wq, *bq, *wkv, *bkv, *wo, *bo,
                *w1, *b1, *w2, *b2, *ag, *ab, *ffg, *ffb;
    if (in_sizes[1] == 1024) {
        ts  = (const float*)d_in[0];
        fg  = (const float*)d_in[1];  fb  = (const float*)d_in[2];
        wq  = (const float*)d_in[3];  bq  = (const float*)d_in[4];
        wkv = (const float*)d_in[5];  bkv = (const float*)d_in[6];
        wo  = (const float*)d_in[7];  bo  = (const float*)d_in[8];
        w1  = (const float*)d_in[9];  b1  = (const float*)d_in[10];
        w2  = (const float*)d_in[11]; b2  = (const float*)d_in[12];
        ag  = (const float*)d_in[13]; ab  = (const float*)d_in[14];
        ffg = (const float*)d_in[15]; ffb = (const float*)d_in[16];
    } else {
        ts  = (const float*)d_in[0];
        wq  = (const float*)d_in[1];  bq  = (const float*)d_in[2];
        wkv = (const float*)d_in[3];  bkv = (const float*)d_in[4];
        wo  = (const float*)d_in[5];  bo  = (const float*)d_in[6];
        w1  = (const float*)d_in[7];  b1  = (const float*)d_in[8];
        w2  = (const float*)d_in[9];  b2  = (const float*)d_in[10];
        ag  = (const float*)d_in[11]; ab  = (const float*)d_in[12];
        ffg = (const float*)d_in[13]; ffb = (const float*)d_in[14];
        fg  = (const float*)d_in[15]; fb  = (const float*)d_in[16];
    }

    float *x;
    __nv_bfloat16 *hh, *hl, *qh_, *ql_, *kvh, *kvl, *ath, *atl, *fh, *fl;
    __nv_bfloat16 *wqkvh, *wqkvl, *woh, *wol, *w1h, *w1l, *w2h, *w2l;
    cudaGetSymbolAddress((void**)&x,    g_x);
    cudaGetSymbolAddress((void**)&hh,   g_h_hi);
    cudaGetSymbolAddress((void**)&hl,   g_h_lo);
    cudaGetSymbolAddress((void**)&qh_,  g_q_hi);
    cudaGetSymbolAddress((void**)&ql_,  g_q_lo);
    cudaGetSymbolAddress((void**)&kvh,  g_kv_hi);
    cudaGetSymbolAddress((void**)&kvl,  g_kv_lo);
    cudaGetSymbolAddress((void**)&ath,  g_att_hi);
    cudaGetSymbolAddress((void**)&atl,  g_att_lo);
    cudaGetSymbolAddress((void**)&fh,   g_f_hi);
    cudaGetSymbolAddress((void**)&fl,   g_f_lo);
    cudaGetSymbolAddress((void**)&wqkvh, g_wqkv_h);
    cudaGetSymbolAddress((void**)&wqkvl, g_wqkv_l);
    cudaGetSymbolAddress((void**)&woh,  g_wo_h);
    cudaGetSymbolAddress((void**)&wol,  g_wo_l);
    cudaGetSymbolAddress((void**)&w1h,  g_w1_h);
    cudaGetSymbolAddress((void**)&w1l,  g_w1_l);
    cudaGetSymbolAddress((void**)&w2h,  g_w2_h);
    cudaGetSymbolAddress((void**)&w2l,  g_w2_l);

    cudaFuncSetAttribute(tgemm_kernel,
                         cudaFuncAttributeMaxDynamicSharedMemorySize, TG_SMEM);
    cudaFuncSetAttribute(fattn_kernel,
                         cudaFuncAttributeMaxDynamicSharedMemorySize, F_SMEM);

    cudaMemcpyAsync(x, ts, sizeof(float) * (size_t)NT * DD,
                    cudaMemcpyDeviceToDevice, 0);

    // weight transpose + split: all layers per weight type (grid.z = NL)
    {
        dim3 blk(32, 8);
        // wq -> rows [0,1024) of packed wqkv ; wkv -> rows [1024,3072)
        wconv_kernel<<<dim3(DD/32, DD/32, NL), blk>>>(
            wq,  wqkvh,             wqkvl,             DD, DD,   (size_t)3*DD*DD);
        wconv_kernel<<<dim3(2*DD/32, DD/32, NL), blk>>>(
            wkv, wqkvh + DD*DD,     wqkvl + DD*DD,     DD, 2*DD, (size_t)3*DD*DD);
        wconv_kernel<<<dim3(DD/32, DD/32, NL), blk>>>(
            wo,  woh,  wol,  DD, DD, (size_t)DD*DD);
        wconv_kernel<<<dim3(FF/32, DD/32, NL), blk>>>(
            w1,  w1h,  w1l,  DD, FF, (size_t)DD*FF);
        wconv_kernel<<<dim3(DD/32, FF/32, NL), blk>>>(
            w2,  w2h,  w2l,  FF, DD, (size_t)FF*DD);
    }

    for (int l = 0; l < NL; l++) {
        ln_bf16_kernel<<<NT, 256>>>(x, ag + (size_t)l*DD, ab + (size_t)l*DD, hh, hl);
        // merged QKV GEMM: M = 3072, Q scaled 1/8 -> q buffers, KV -> kv buffers
        tgemm_kernel<<<dim3(3*DD/128, NT/128), 256, TG_SMEM>>>(
            hh, hl, wqkvh + (size_t)l*3*DD*DD, wqkvl + (size_t)l*3*DD*DD,
            bq + (size_t)l*DD, bkv + (size_t)l*2*DD, nullptr,
            nullptr, qh_, ql_, kvh, kvl, DD, 3*DD, 4);
        fattn_kernel<<<dim3(SSEQ/128, BB*HH), 256, F_SMEM>>>(
            qh_, ql_, kvh, kvl, ath, atl);
        // x = heads@wo + bo + x
        tgemm_kernel<<<dim3(DD/128, NT/128), 256, TG_SMEM>>>(
            ath, atl, woh + (size_t)l*DD*DD, wol + (size_t)l*DD*DD,
            bo + (size_t)l*DD, nullptr, x,
            x, nullptr, nullptr, nullptr, nullptr, DD, DD, 2);
        ln_bf16_kernel<<<NT, 256>>>(x, ffg + (size_t)l*DD, ffb + (size_t)l*DD, hh, hl);
        // f = softplus(h@w1 + b1) -> bf16 split
        tgemm_kernel<<<dim3(FF/128, NT/128), 256, TG_SMEM>>>(
            hh, hl, w1h + (size_t)l*DD*FF, w1l + (size_t)l*DD*FF,
            b1 + (size_t)l*FF, nullptr, nullptr,
            nullptr, fh, fl, nullptr, nullptr, DD, FF, 1);
        // x = f@w2 + b2 + x
        tgemm_kernel<<<dim3(DD/128, NT/128), 256, TG_SMEM>>>(
            fh, fl, w2h + (size_t)l*FF*DD, w2l + (size_t)l*FF*DD,
            b2 + (size_t)l*DD, nullptr, x,
            x, nullptr, nullptr, nullptr, nullptr, FF, DD, 2);
    }

    ln_kernel<<<NT, 256>>>(x, fg, fb, (float*)d_out);
}